// round 4
// baseline (speedup 1.0000x reference)
#include <cuda_runtime.h>
#include <cuda_bf16.h>
#include <cstdint>
#include <cstring>

#define N_OBJ 50000
#define N_REL 200000
#define FEAT 1024
#define INTER 512
#define EMB 200
#define N_CLS 151
#define N_PRED 51

typedef __nv_bfloat16 bf16;

// ---------------- scratch (module-load allocated, allowed) ----------------
// bf16 hi/lo activation buffers
__device__ bf16 g_frel_hi[(size_t)N_REL * FEAT];
__device__ bf16 g_frel_lo[(size_t)N_REL * FEAT];
__device__ bf16 g_fobj_hi[(size_t)N_OBJ * FEAT];
__device__ bf16 g_fobj_lo[(size_t)N_OBJ * FEAT];
__device__ bf16 g_h1r_hi[(size_t)N_REL * INTER];
__device__ bf16 g_h1r_lo[(size_t)N_REL * INTER];
__device__ bf16 g_h1o_hi[(size_t)N_OBJ * INTER];
__device__ bf16 g_h1o_lo[(size_t)N_OBJ * INTER];
__device__ bf16 g_pri_hi[(size_t)N_REL * EMB];
__device__ bf16 g_pri_lo[(size_t)N_REL * EMB];
__device__ bf16 g_soi_hi[(size_t)N_OBJ * EMB];
__device__ bf16 g_soi_lo[(size_t)N_OBJ * EMB];
__device__ bf16 g_paf_hi[(size_t)N_REL * EMB];
__device__ bf16 g_paf_lo[(size_t)N_REL * EMB];
__device__ bf16 g_soo_hi[(size_t)N_OBJ * EMB];
__device__ bf16 g_soo_lo[(size_t)N_OBJ * EMB];
__device__ bf16 g_hpo_hi[(size_t)N_REL * EMB];
__device__ bf16 g_hpo_lo[(size_t)N_REL * EMB];
__device__ bf16 g_pe_hi[N_PRED * EMB];
__device__ bf16 g_pe_lo[N_PRED * EMB];
__device__ bf16 g_oe_hi[N_CLS * EMB];
__device__ bf16 g_oe_lo[N_CLS * EMB];
// weight hi/lo buffers
__device__ bf16 g_wrs_hi[EMB * EMB],    g_wrs_lo[EMB * EMB];
__device__ bf16 g_wos_hi[EMB * EMB],    g_wos_lo[EMB * EMB];
__device__ bf16 g_wso1_hi[INTER * FEAT],g_wso1_lo[INTER * FEAT];
__device__ bf16 g_wso2_hi[EMB * INTER], g_wso2_lo[EMB * INTER];
__device__ bf16 g_wsoo_hi[EMB * EMB],   g_wsoo_lo[EMB * EMB];
__device__ bf16 g_wp1_hi[INTER * FEAT], g_wp1_lo[INTER * FEAT];
__device__ bf16 g_wp2_hi[EMB * INTER],  g_wp2_lo[EMB * INTER];
__device__ bf16 g_wpip_hi[EMB * EMB],   g_wpip_lo[EMB * EMB];
__device__ bf16 g_wcmb_hi[EMB * EMB],   g_wcmb_lo[EMB * EMB];
__device__ bf16 g_w1s_hi[EMB * EMB],    g_w1s_lo[EMB * EMB];
__device__ bf16 g_w1p_hi[EMB * EMB],    g_w1p_lo[EMB * EMB];
__device__ bf16 g_w1o_hi[EMB * EMB],    g_w1o_lo[EMB * EMB];
__device__ bf16 g_wpo2_hi[EMB * EMB],   g_wpo2_lo[EMB * EMB];
// fp32 intermediates
__device__ float g_Acomb[(size_t)N_OBJ * EMB];
__device__ float g_tmpP[(size_t)N_REL * EMB];
__device__ float g_Bs[(size_t)N_OBJ * EMB];
__device__ float g_Bo[(size_t)N_OBJ * EMB];
__device__ float g_tmpQ[(size_t)N_REL * EMB];

// ---------------- helpers ----------------
__device__ __forceinline__ uint32_t smem_u32(const void* p) {
    uint32_t a;
    asm("{ .reg .u64 t; cvta.to.shared.u64 t, %1; cvt.u32.u64 %0, t; }" : "=r"(a) : "l"(p));
    return a;
}

__device__ __forceinline__ void ldsm_x4(uint32_t& r0, uint32_t& r1, uint32_t& r2, uint32_t& r3,
                                        uint32_t addr) {
    asm volatile("ldmatrix.sync.aligned.m8n8.x4.shared.b16 {%0,%1,%2,%3}, [%4];"
                 : "=r"(r0), "=r"(r1), "=r"(r2), "=r"(r3) : "r"(addr));
}

__device__ __forceinline__ void mma_bf16(float* c, const uint32_t* a, uint32_t b0, uint32_t b1) {
    asm volatile("mma.sync.aligned.m16n8k16.row.col.f32.bf16.bf16.f32 "
                 "{%0,%1,%2,%3}, {%4,%5,%6,%7}, {%8,%9}, {%0,%1,%2,%3};"
                 : "+f"(c[0]), "+f"(c[1]), "+f"(c[2]), "+f"(c[3])
                 : "r"(a[0]), "r"(a[1]), "r"(a[2]), "r"(a[3]), "r"(b0), "r"(b1));
}

__device__ __forceinline__ void cp16(uint32_t dst, const void* src, bool valid) {
    int sz = valid ? 16 : 0;
    asm volatile("cp.async.cg.shared.global [%0], [%1], 16, %2;"
                 :: "r"(dst), "l"(src), "r"(sz) : "memory");
}
#define CP_COMMIT() asm volatile("cp.async.commit_group;" ::: "memory")
#define CP_WAIT1()  asm volatile("cp.async.wait_group 1;" ::: "memory")

__device__ __forceinline__ void split2(float x, float y, uint32_t& hi, uint32_t& lo) {
    __nv_bfloat162 h = __floats2bfloat162_rn(x, y);
    __nv_bfloat162 l = __floats2bfloat162_rn(x - __bfloat162float(h.x),
                                             y - __bfloat162float(h.y));
    memcpy(&hi, &h, 4); memcpy(&lo, &l, 4);
}

// ---------------- HMMA bf16 split GEMM, pre-converted operands ----------
// CTA 128x128, BK=32 bf16; 8 warps (4M x 2N), warp tile 32x64
// smem: 2 stages x 4 tiles (Ah, Al, Bh, Bl), rows padded to 80B
#define ROWB 80
#define TILE_B (128 * ROWB)
#define STAGE_B (4 * TILE_B)
#define SMEM_TOT (2 * STAGE_B)

__global__ __launch_bounds__(256)
void hmma2(const bf16* __restrict__ Ahi, const bf16* __restrict__ Alo,
           const bf16* __restrict__ Whi, const bf16* __restrict__ Wlo,
           const float* __restrict__ bias,
           float* __restrict__ C, bf16* __restrict__ Chi, bf16* __restrict__ Clo,
           int M, int N, int K, int relu, int wf32, int whilo, int hbias)
{
    extern __shared__ __align__(16) char smem[];
    const uint32_t base = smem_u32(smem);

    const int tid = threadIdx.x;
    const int lane = tid & 31;
    const int wid = tid >> 5;
    const int wm = wid & 3;
    const int wn = wid >> 2;
    const int m0 = blockIdx.x * 128;
    const int n0 = blockIdx.y * 128;

    const int lrA = (lane & 7) + ((lane >> 3) & 1) * 8;
    const int wA  = lane >> 4;
    const int lrB = (lane & 7) + ((lane >> 4) << 3);
    const int wB  = (lane >> 3) & 1;
    const int gid = lane >> 2, tig = lane & 3;

    float c[2][8][4];
#pragma unroll
    for (int i = 0; i < 2; i++)
#pragma unroll
        for (int j = 0; j < 8; j++)
#pragma unroll
            for (int q = 0; q < 4; q++) c[i][j][q] = 0.f;

    const int nkb = (K + 31) >> 5;

    // stage loader: 2048 16B-chunks -> 8 per thread
    auto load_stage = [&](int stage, int k0) {
        const uint32_t stg = base + (uint32_t)stage * STAGE_B;
#pragma unroll
        for (int i = 0; i < 8; i++) {
            int idx = tid + i * 256;
            int ch = idx & 3;
            int r  = (idx >> 2) & 127;
            int t4 = idx >> 9;                  // 0:Ah 1:Al 2:Bh 3:Bl
            uint32_t dst = stg + (uint32_t)t4 * TILE_B + (uint32_t)(r * ROWB + ch * 16);
            int ke = k0 + ch * 8;
            const bf16* sp;
            bool v;
            if (t4 < 2) {
                v = (m0 + r < M) && (ke < K);
                const bf16* pb = (t4 == 0) ? Ahi : Alo;
                int rr = (m0 + r < M) ? (m0 + r) : 0;
                sp = pb + (size_t)rr * K + ke;
            } else {
                v = (n0 + r < N) && (ke < K);
                const bf16* pb = (t4 == 2) ? Whi : Wlo;
                int rr = (n0 + r < N) ? (n0 + r) : 0;
                sp = pb + (size_t)rr * K + ke;
            }
            cp16(dst, sp, v);
        }
    };

    load_stage(0, 0);
    CP_COMMIT();

    for (int kb = 0; kb < nkb; kb++) {
        if (kb + 1 < nkb) load_stage((kb + 1) & 1, (kb + 1) << 5);
        CP_COMMIT();
        CP_WAIT1();
        __syncthreads();

        const uint32_t stg = base + (uint32_t)(kb & 1) * STAGE_B;
        const uint32_t sAh = stg, sAl = stg + TILE_B;
        const uint32_t sBh = stg + 2 * TILE_B, sBl = stg + 3 * TILE_B;

#pragma unroll
        for (int kc = 0; kc < 2; kc++) {
            const uint32_t acol = (uint32_t)((2 * kc + wA) * 16);
            const uint32_t bcol = (uint32_t)((2 * kc + wB) * 16);
            uint32_t ah[2][4], al[2][4];
#pragma unroll
            for (int mt = 0; mt < 2; mt++) {
                uint32_t ro = (uint32_t)((wm * 32 + mt * 16 + lrA) * ROWB);
                ldsm_x4(ah[mt][0], ah[mt][1], ah[mt][2], ah[mt][3], sAh + ro + acol);
                ldsm_x4(al[mt][0], al[mt][1], al[mt][2], al[mt][3], sAl + ro + acol);
            }
            uint32_t bh[4][4], bl[4][4];
#pragma unroll
            for (int nt = 0; nt < 4; nt++) {
                uint32_t ro = (uint32_t)((wn * 64 + nt * 16 + lrB) * ROWB);
                ldsm_x4(bh[nt][0], bh[nt][1], bh[nt][2], bh[nt][3], sBh + ro + bcol);
                ldsm_x4(bl[nt][0], bl[nt][1], bl[nt][2], bl[nt][3], sBl + ro + bcol);
            }
#pragma unroll
            for (int mt = 0; mt < 2; mt++)
#pragma unroll
                for (int nt = 0; nt < 8; nt++) {
                    const int nn = nt >> 1, oc = (nt & 1) * 2;
                    mma_bf16(c[mt][nt], ah[mt], bh[nn][oc], bh[nn][oc + 1]);
                }
#pragma unroll
            for (int mt = 0; mt < 2; mt++)
#pragma unroll
                for (int nt = 0; nt < 8; nt++) {
                    const int nn = nt >> 1, oc = (nt & 1) * 2;
                    mma_bf16(c[mt][nt], ah[mt], bl[nn][oc], bl[nn][oc + 1]);
                }
#pragma unroll
            for (int mt = 0; mt < 2; mt++)
#pragma unroll
                for (int nt = 0; nt < 8; nt++) {
                    const int nn = nt >> 1, oc = (nt & 1) * 2;
                    mma_bf16(c[mt][nt], al[mt], bh[nn][oc], bh[nn][oc + 1]);
                }
        }
        __syncthreads();
    }

    // epilogue
#pragma unroll
    for (int nt = 0; nt < 8; nt++) {
        const int col = n0 + wn * 64 + nt * 8 + tig * 2;
        if (col >= N) continue;
        float2 bb = make_float2(0.f, 0.f);
        if (hbias) bb = *(const float2*)(bias + col);
#pragma unroll
        for (int mt = 0; mt < 2; mt++) {
            const int r0 = m0 + wm * 32 + mt * 16 + gid;
            float v0 = c[mt][nt][0] + bb.x, v1 = c[mt][nt][1] + bb.y;
            float v2 = c[mt][nt][2] + bb.x, v3 = c[mt][nt][3] + bb.y;
            if (relu) {
                v0 = fmaxf(v0, 0.f); v1 = fmaxf(v1, 0.f);
                v2 = fmaxf(v2, 0.f); v3 = fmaxf(v3, 0.f);
            }
            if (r0 < M) {
                size_t o = (size_t)r0 * N + col;
                if (wf32) *(float2*)(C + o) = make_float2(v0, v1);
                if (whilo) {
                    uint32_t h, l; split2(v0, v1, h, l);
                    *(uint32_t*)(Chi + o) = h; *(uint32_t*)(Clo + o) = l;
                }
            }
            if (r0 + 8 < M) {
                size_t o = (size_t)(r0 + 8) * N + col;
                if (wf32) *(float2*)(C + o) = make_float2(v2, v3);
                if (whilo) {
                    uint32_t h, l; split2(v2, v3, h, l);
                    *(uint32_t*)(Chi + o) = h; *(uint32_t*)(Clo + o) = l;
                }
            }
        }
    }
}

// ---------------- conversion / elementwise kernels ----------------
__global__ void conv_hilo(const float4* __restrict__ src, uint32_t* __restrict__ hi,
                          uint32_t* __restrict__ lo, size_t n4)
{
    size_t t = (size_t)blockIdx.x * blockDim.x + threadIdx.x;
    if (t >= n4) return;
    float4 v = src[t];
    uint32_t h0, l0, h1, l1;
    split2(v.x, v.y, h0, l0);
    split2(v.z, v.w, h1, l1);
    hi[t * 2] = h0; hi[t * 2 + 1] = h1;
    lo[t * 2] = l0; lo[t * 2 + 1] = l1;
}

__global__ void conv_w(const float* __restrict__ src, int lds,
                       bf16* __restrict__ hi, bf16* __restrict__ lo, int N, int K)
{
    int t = blockIdx.x * blockDim.x + threadIdx.x;
    if (t >= N * K) return;
    int r = t / K, cc = t % K;
    float v = src[(size_t)r * lds + cc];
    bf16 h = __float2bfloat16(v);
    hi[t] = h;
    lo[t] = __float2bfloat16(v - __bfloat162float(h));
}

__global__ void combine_wpi_hilo(const float* __restrict__ Wpi,
                                 bf16* __restrict__ hi, bf16* __restrict__ lo)
{
    int t = blockIdx.x * blockDim.x + threadIdx.x;
    if (t >= EMB * EMB) return;
    int r = t / EMB, cc = t % EMB;
    float v = Wpi[r * 600 + cc] + Wpi[r * 600 + 400 + cc];
    bf16 h = __float2bfloat16(v);
    hi[t] = h;
    lo[t] = __float2bfloat16(v - __bfloat162float(h));
}

__global__ void gather_rows_f4(const float* __restrict__ src, const int* __restrict__ idx,
                               float* __restrict__ dst, int nrows)
{
    const int C4 = EMB / 4;
    int t = blockIdx.x * blockDim.x + threadIdx.x;
    if (t >= nrows * C4) return;
    int r = t / C4, cc = t % C4;
    ((float4*)dst)[t] = ((const float4*)src)[(size_t)idx[r] * C4 + cc];
}

// pred_af = relu(tmpP + Acomb[sub] + bpi) -> hi/lo
__global__ void fuse_pi_hilo(const float* __restrict__ tmpP, const float* __restrict__ Acomb,
                             const int* __restrict__ rel_inds, const float* __restrict__ bias,
                             uint32_t* __restrict__ ohi, uint32_t* __restrict__ olo)
{
    const int C4 = EMB / 4;
    int t = blockIdx.x * blockDim.x + threadIdx.x;
    if (t >= N_REL * C4) return;
    int r = t / C4, cc = t % C4;
    int s = rel_inds[r * 3 + 1];
    float4 p = ((const float4*)tmpP)[t];
    float4 a = ((const float4*)Acomb)[(size_t)s * C4 + cc];
    float4 b = ((const float4*)bias)[cc];
    float v0 = fmaxf(p.x + a.x + b.x, 0.f), v1 = fmaxf(p.y + a.y + b.y, 0.f);
    float v2 = fmaxf(p.z + a.z + b.z, 0.f), v3 = fmaxf(p.w + a.w + b.w, 0.f);
    uint32_t h0, l0, h1, l1;
    split2(v0, v1, h0, l0); split2(v2, v3, h1, l1);
    ohi[t * 2] = h0; ohi[t * 2 + 1] = h1;
    olo[t * 2] = l0; olo[t * 2 + 1] = l1;
}

// hpo = relu(tmpQ + Bs[sub] + Bo[obj] + bpo1) -> hi/lo
__global__ void fuse_po_hilo(const float* __restrict__ tmpQ, const float* __restrict__ Bsub,
                             const float* __restrict__ Bobj, const int* __restrict__ rel_inds,
                             const float* __restrict__ bias,
                             uint32_t* __restrict__ ohi, uint32_t* __restrict__ olo)
{
    const int C4 = EMB / 4;
    int t = blockIdx.x * blockDim.x + threadIdx.x;
    if (t >= N_REL * C4) return;
    int r = t / C4, cc = t % C4;
    int s = rel_inds[r * 3 + 1];
    int o = rel_inds[r * 3 + 2];
    float4 q  = ((const float4*)tmpQ)[t];
    float4 bs = ((const float4*)Bsub)[(size_t)s * C4 + cc];
    float4 bo = ((const float4*)Bobj)[(size_t)o * C4 + cc];
    float4 b  = ((const float4*)bias)[cc];
    float v0 = fmaxf(q.x + bs.x + bo.x + b.x, 0.f), v1 = fmaxf(q.y + bs.y + bo.y + b.y, 0.f);
    float v2 = fmaxf(q.z + bs.z + bo.z + b.z, 0.f), v3 = fmaxf(q.w + bs.w + bo.w + b.w, 0.f);
    uint32_t h0, l0, h1, l1;
    split2(v0, v1, h0, l0); split2(v2, v3, h1, l1);
    ohi[t * 2] = h0; ohi[t * 2 + 1] = h1;
    olo[t * 2] = l0; olo[t * 2 + 1] = l1;
}

// ---------------- host side ----------------
template <typename T>
static T* sym(const void* s)
{
    void* p = nullptr;
    cudaGetSymbolAddress(&p, s);
    return (T*)p;
}

static void gemm2(const bf16* Ahi, const bf16* Alo, const bf16* Whi, const bf16* Wlo,
                  const float* bias, float* C, bf16* Chi, bf16* Clo,
                  int M, int N, int K, bool relu)
{
    static bool attr_set = false;
    if (!attr_set) {
        cudaFuncSetAttribute(hmma2, cudaFuncAttributeMaxDynamicSharedMemorySize, SMEM_TOT);
        attr_set = true;
    }
    dim3 grid((M + 127) / 128, (N + 127) / 128), block(256);
    hmma2<<<grid, block, SMEM_TOT>>>(Ahi, Alo, Whi, Wlo, bias, C, Chi, Clo,
                                     M, N, K, relu ? 1 : 0, C ? 1 : 0, Chi ? 1 : 0,
                                     bias ? 1 : 0);
}

static void convw(const float* src, int lds, bf16* hi, bf16* lo, int N, int K)
{
    int n = N * K;
    conv_w<<<(n + 255) / 256, 256>>>(src, lds, hi, lo, N, K);
}

extern "C" void kernel_launch(void* const* d_in, const int* in_sizes, int n_in,
                              void* d_out, int out_size)
{
    (void)in_sizes; (void)n_in; (void)out_size;

    const float* obj_feats  = (const float*)d_in[1];
    const float* rel_feats  = (const float*)d_in[2];
    const int*   rel_inds   = (const int*)d_in[4];
    const int*   gt_rel     = (const int*)d_in[5];
    const int*   gt_obj     = (const int*)d_in[6];
    const float* obj_embed  = (const float*)d_in[7];
    const float* pred_embed = (const float*)d_in[8];
    const float* Wrs = (const float*)d_in[9];  const float* brs = (const float*)d_in[10];
    const float* Wos = (const float*)d_in[11]; const float* bos = (const float*)d_in[12];
    const float* Wso1= (const float*)d_in[13]; const float* bso1= (const float*)d_in[14];
    const float* Wso2= (const float*)d_in[15]; const float* bso2= (const float*)d_in[16];
    const float* Wsoo= (const float*)d_in[17]; const float* bsoo= (const float*)d_in[18];
    const float* Wp1 = (const float*)d_in[19]; const float* bp1 = (const float*)d_in[20];
    const float* Wp2 = (const float*)d_in[21]; const float* bp2 = (const float*)d_in[22];
    const float* Wpi = (const float*)d_in[23]; const float* bpi = (const float*)d_in[24];
    const float* Wpo1= (const float*)d_in[25]; const float* bpo1= (const float*)d_in[26];
    const float* Wpo2= (const float*)d_in[27]; const float* bpo2= (const float*)d_in[28];

    float* out = (float*)d_out;
    float* o_so_out   = out;                      // [50000,200]
    float* o_pred_out = out + 10000000;           // [200000,200]
    float* o_rel_sem  = out + 50000000;           // [200000,200]
    float* o_obj_sem  = out + 90000000;           // [50000,200]
    float* o_rel_gt   = out + 100000000;          // [51,200]
    float* o_obj_gt   = out + 100010200;          // [151,200]

    bf16 *frel_hi = sym<bf16>(g_frel_hi), *frel_lo = sym<bf16>(g_frel_lo);
    bf16 *fobj_hi = sym<bf16>(g_fobj_hi), *fobj_lo = sym<bf16>(g_fobj_lo);
    bf16 *h1r_hi  = sym<bf16>(g_h1r_hi),  *h1r_lo  = sym<bf16>(g_h1r_lo);
    bf16 *h1o_hi  = sym<bf16>(g_h1o_hi),  *h1o_lo  = sym<bf16>(g_h1o_lo);
    bf16 *pri_hi  = sym<bf16>(g_pri_hi),  *pri_lo  = sym<bf16>(g_pri_lo);
    bf16 *soi_hi  = sym<bf16>(g_soi_hi),  *soi_lo  = sym<bf16>(g_soi_lo);
    bf16 *paf_hi  = sym<bf16>(g_paf_hi),  *paf_lo  = sym<bf16>(g_paf_lo);
    bf16 *soo_hi  = sym<bf16>(g_soo_hi),  *soo_lo  = sym<bf16>(g_soo_lo);
    bf16 *hpo_hi  = sym<bf16>(g_hpo_hi),  *hpo_lo  = sym<bf16>(g_hpo_lo);
    bf16 *pe_hi = sym<bf16>(g_pe_hi), *pe_lo = sym<bf16>(g_pe_lo);
    bf16 *oe_hi = sym<bf16>(g_oe_hi), *oe_lo = sym<bf16>(g_oe_lo);
    bf16 *wrs_hi = sym<bf16>(g_wrs_hi), *wrs_lo = sym<bf16>(g_wrs_lo);
    bf16 *wos_hi = sym<bf16>(g_wos_hi), *wos_lo = sym<bf16>(g_wos_lo);
    bf16 *wso1_hi= sym<bf16>(g_wso1_hi),*wso1_lo= sym<bf16>(g_wso1_lo);
    bf16 *wso2_hi= sym<bf16>(g_wso2_hi),*wso2_lo= sym<bf16>(g_wso2_lo);
    bf16 *wsoo_hi= sym<bf16>(g_wsoo_hi),*wsoo_lo= sym<bf16>(g_wsoo_lo);
    bf16 *wp1_hi = sym<bf16>(g_wp1_hi), *wp1_lo = sym<bf16>(g_wp1_lo);
    bf16 *wp2_hi = sym<bf16>(g_wp2_hi), *wp2_lo = sym<bf16>(g_wp2_lo);
    bf16 *wpip_hi= sym<bf16>(g_wpip_hi),*wpip_lo= sym<bf16>(g_wpip_lo);
    bf16 *wcmb_hi= sym<bf16>(g_wcmb_hi),*wcmb_lo= sym<bf16>(g_wcmb_lo);
    bf16 *w1s_hi = sym<bf16>(g_w1s_hi), *w1s_lo = sym<bf16>(g_w1s_lo);
    bf16 *w1p_hi = sym<bf16>(g_w1p_hi), *w1p_lo = sym<bf16>(g_w1p_lo);
    bf16 *w1o_hi = sym<bf16>(g_w1o_hi), *w1o_lo = sym<bf16>(g_w1o_lo);
    bf16 *wpo2_hi= sym<bf16>(g_wpo2_hi),*wpo2_lo= sym<bf16>(g_wpo2_lo);
    float *Acomb = sym<float>(g_Acomb), *tmpP = sym<float>(g_tmpP);
    float *Bs = sym<float>(g_Bs), *Bo = sym<float>(g_Bo), *tmpQ = sym<float>(g_tmpQ);

    // ---- conversions (once) ----
    {
        size_t n4 = (size_t)N_REL * FEAT / 4;
        conv_hilo<<<(int)((n4 + 255) / 256), 256>>>((const float4*)rel_feats,
                                                    (uint32_t*)frel_hi, (uint32_t*)frel_lo, n4);
        n4 = (size_t)N_OBJ * FEAT / 4;
        conv_hilo<<<(int)((n4 + 255) / 256), 256>>>((const float4*)obj_feats,
                                                    (uint32_t*)fobj_hi, (uint32_t*)fobj_lo, n4);
        n4 = (size_t)N_PRED * EMB / 4;
        conv_hilo<<<(int)((n4 + 255) / 256), 256>>>((const float4*)pred_embed,
                                                    (uint32_t*)pe_hi, (uint32_t*)pe_lo, n4);
        n4 = (size_t)N_CLS * EMB / 4;
        conv_hilo<<<(int)((n4 + 255) / 256), 256>>>((const float4*)obj_embed,
                                                    (uint32_t*)oe_hi, (uint32_t*)oe_lo, n4);
    }
    convw(Wrs, EMB, wrs_hi, wrs_lo, EMB, EMB);
    convw(Wos, EMB, wos_hi, wos_lo, EMB, EMB);
    convw(Wso1, FEAT, wso1_hi, wso1_lo, INTER, FEAT);
    convw(Wso2, INTER, wso2_hi, wso2_lo, EMB, INTER);
    convw(Wsoo, EMB, wsoo_hi, wsoo_lo, EMB, EMB);
    convw(Wp1, FEAT, wp1_hi, wp1_lo, INTER, FEAT);
    convw(Wp2, INTER, wp2_hi, wp2_lo, EMB, INTER);
    convw(Wpi + EMB, 600, wpip_hi, wpip_lo, EMB, EMB);
    convw(Wpo1, 600, w1s_hi, w1s_lo, EMB, EMB);
    convw(Wpo1 + EMB, 600, w1p_hi, w1p_lo, EMB, EMB);
    convw(Wpo1 + 2 * EMB, 600, w1o_hi, w1o_lo, EMB, EMB);
    convw(Wpo2, EMB, wpo2_hi, wpo2_lo, EMB, EMB);
    combine_wpi_hilo<<<(EMB * EMB + 255) / 256, 256>>>(Wpi, wcmb_hi, wcmb_lo);

    // ---- semantic tables + gathers ----
    gemm2(pe_hi, pe_lo, wrs_hi, wrs_lo, brs, o_rel_gt, nullptr, nullptr,
          N_PRED, EMB, EMB, false);
    gemm2(oe_hi, oe_lo, wos_hi, wos_lo, bos, o_obj_gt, nullptr, nullptr,
          N_CLS, EMB, EMB, false);
    gather_rows_f4<<<(N_REL * (EMB / 4) + 255) / 256, 256>>>(o_rel_gt, gt_rel, o_rel_sem, N_REL);
    gather_rows_f4<<<(N_OBJ * (EMB / 4) + 255) / 256, 256>>>(o_obj_gt, gt_obj, o_obj_sem, N_OBJ);

    // ---- object path ----
    gemm2(fobj_hi, fobj_lo, wso1_hi, wso1_lo, bso1, nullptr, h1o_hi, h1o_lo,
          N_OBJ, INTER, FEAT, true);
    gemm2(h1o_hi, h1o_lo, wso2_hi, wso2_lo, bso2, nullptr, soi_hi, soi_lo,
          N_OBJ, EMB, INTER, true);
    gemm2(soi_hi, soi_lo, wsoo_hi, wsoo_lo, bsoo, o_so_out, soo_hi, soo_lo,
          N_OBJ, EMB, EMB, false);

    // ---- relation path ----
    gemm2(frel_hi, frel_lo, wp1_hi, wp1_lo, bp1, nullptr, h1r_hi, h1r_lo,
          N_REL, INTER, FEAT, true);
    gemm2(h1r_hi, h1r_lo, wp2_hi, wp2_lo, bp2, nullptr, pri_hi, pri_lo,
          N_REL, EMB, INTER, true);

    // ---- pred_inter_af (factored concat) ----
    gemm2(soi_hi, soi_lo, wcmb_hi, wcmb_lo, nullptr, Acomb, nullptr, nullptr,
          N_OBJ, EMB, EMB, false);
    gemm2(pri_hi, pri_lo, wpip_hi, wpip_lo, nullptr, tmpP, nullptr, nullptr,
          N_REL, EMB, EMB, false);
    fuse_pi_hilo<<<(N_REL * (EMB / 4) + 255) / 256, 256>>>(
        tmpP, Acomb, rel_inds, bpi, (uint32_t*)paf_hi, (uint32_t*)paf_lo);

    // ---- pred_out (factored concat) ----
    gemm2(soo_hi, soo_lo, w1s_hi, w1s_lo, nullptr, Bs, nullptr, nullptr,
          N_OBJ, EMB, EMB, false);
    gemm2(soo_hi, soo_lo, w1o_hi, w1o_lo, nullptr, Bo, nullptr, nullptr,
          N_OBJ, EMB, EMB, false);
    gemm2(paf_hi, paf_lo, w1p_hi, w1p_lo, nullptr, tmpQ, nullptr, nullptr,
          N_REL, EMB, EMB, false);
    fuse_po_hilo<<<(N_REL * (EMB / 4) + 255) / 256, 256>>>(
        tmpQ, Bs, Bo, rel_inds, bpo1, (uint32_t*)hpo_hi, (uint32_t*)hpo_lo);
    gemm2(hpo_hi, hpo_lo, wpo2_hi, wpo2_lo, bpo2, o_pred_out, nullptr, nullptr,
          N_REL, EMB, EMB, false);
}

// round 5
// speedup vs baseline: 1.6578x; 1.6578x over previous
#include <cuda_runtime.h>
#include <cuda_fp16.h>
#include <cstdint>
#include <cstring>

#define N_OBJ 50000
#define N_REL 200000
#define FEAT 1024
#define INTER 512
#define EMB 200
#define N_CLS 151
#define N_PRED 51

typedef __half half_t;

// ---------------- scratch ----------------
// fp16 activations (single precision copy)
__device__ half_t g_frel_h[(size_t)N_REL * FEAT];
__device__ half_t g_fobj_h[(size_t)N_OBJ * FEAT];
__device__ half_t g_h1r_h[(size_t)N_REL * INTER];
__device__ half_t g_h1o_h[(size_t)N_OBJ * INTER];
__device__ half_t g_pri_h[(size_t)N_REL * EMB];
__device__ half_t g_soi_h[(size_t)N_OBJ * EMB];
__device__ half_t g_paf_h[(size_t)N_REL * EMB];
__device__ half_t g_soo_h[(size_t)N_OBJ * EMB];
__device__ half_t g_hpo_h[(size_t)N_REL * EMB];
__device__ half_t g_pe_h[N_PRED * EMB];
__device__ half_t g_oe_h[N_CLS * EMB];
// fp16 hi/lo weights
__device__ half_t g_wrs_hi[EMB * EMB],    g_wrs_lo[EMB * EMB];
__device__ half_t g_wos_hi[EMB * EMB],    g_wos_lo[EMB * EMB];
__device__ half_t g_wso1_hi[INTER * FEAT],g_wso1_lo[INTER * FEAT];
__device__ half_t g_wso2_hi[EMB * INTER], g_wso2_lo[EMB * INTER];
__device__ half_t g_wsoo_hi[EMB * EMB],   g_wsoo_lo[EMB * EMB];
__device__ half_t g_wp1_hi[INTER * FEAT], g_wp1_lo[INTER * FEAT];
__device__ half_t g_wp2_hi[EMB * INTER],  g_wp2_lo[EMB * INTER];
__device__ half_t g_wpip_hi[EMB * EMB],   g_wpip_lo[EMB * EMB];
__device__ half_t g_wcmb_hi[EMB * EMB],   g_wcmb_lo[EMB * EMB];
__device__ half_t g_w1s_hi[EMB * EMB],    g_w1s_lo[EMB * EMB];
__device__ half_t g_w1p_hi[EMB * EMB],    g_w1p_lo[EMB * EMB];
__device__ half_t g_w1o_hi[EMB * EMB],    g_w1o_lo[EMB * EMB];
__device__ half_t g_wpo2_hi[EMB * EMB],   g_wpo2_lo[EMB * EMB];
// fp32 intermediates
__device__ float g_Acomb[(size_t)N_OBJ * EMB];
__device__ float g_tmpP[(size_t)N_REL * EMB];
__device__ float g_Bs[(size_t)N_OBJ * EMB];
__device__ float g_Bo[(size_t)N_OBJ * EMB];
__device__ float g_tmpQ[(size_t)N_REL * EMB];

// ---------------- device helpers ----------------
__device__ __forceinline__ uint32_t smem_u32(const void* p) {
    uint32_t a;
    asm("{ .reg .u64 t; cvta.to.shared.u64 t, %1; cvt.u32.u64 %0, t; }" : "=r"(a) : "l"(p));
    return a;
}

__device__ __forceinline__ void ldsm_x4(uint32_t& r0, uint32_t& r1, uint32_t& r2, uint32_t& r3,
                                        uint32_t addr) {
    asm volatile("ldmatrix.sync.aligned.m8n8.x4.shared.b16 {%0,%1,%2,%3}, [%4];"
                 : "=r"(r0), "=r"(r1), "=r"(r2), "=r"(r3) : "r"(addr));
}

__device__ __forceinline__ void mma_f16(float* c, const uint32_t* a, uint32_t b0, uint32_t b1) {
    asm volatile("mma.sync.aligned.m16n8k16.row.col.f32.f16.f16.f32 "
                 "{%0,%1,%2,%3}, {%4,%5,%6,%7}, {%8,%9}, {%0,%1,%2,%3};"
                 : "+f"(c[0]), "+f"(c[1]), "+f"(c[2]), "+f"(c[3])
                 : "r"(a[0]), "r"(a[1]), "r"(a[2]), "r"(a[3]), "r"(b0), "r"(b1));
}

__device__ __forceinline__ void cp16(uint32_t dst, const void* src, bool valid) {
    int sz = valid ? 16 : 0;
    asm volatile("cp.async.cg.shared.global [%0], [%1], 16, %2;"
                 :: "r"(dst), "l"(src), "r"(sz) : "memory");
}
#define CP_COMMIT() asm volatile("cp.async.commit_group;" ::: "memory")
#define CP_WAIT1()  asm volatile("cp.async.wait_group 1;" ::: "memory")

__device__ __forceinline__ uint32_t pack_h2(float x, float y) {
    __half2 h = __floats2half2_rn(x, y);
    uint32_t u; memcpy(&u, &h, 4); return u;
}

// ---------------- fp16 2-pass GEMM: C = act(A[M,K] @ W[N,K]^T + bias) ----
// W exact as hi+lo; A single fp16. CTA 128x128, BK=32, 8 warps (4M x 2N).
#define ROWB 80
#define TILE_B (128 * ROWB)      // 10240
#define STAGE_B (3 * TILE_B)     // A, Bh, Bl
#define SMEM_TOT (2 * STAGE_B)   // 61440

__global__ __launch_bounds__(256, 2)
void hmma_h(const half_t* __restrict__ A,
            const half_t* __restrict__ Whi, const half_t* __restrict__ Wlo,
            const float* __restrict__ bias,
            float* __restrict__ C, half_t* __restrict__ Ch,
            int M, int N, int K, int relu, int wf32, int wf16, int hbias)
{
    extern __shared__ __align__(16) char smem[];
    const uint32_t base = smem_u32(smem);

    const int tid = threadIdx.x;
    const int lane = tid & 31;
    const int wid = tid >> 5;
    const int wm = wid & 3;
    const int wn = wid >> 2;
    const int m0 = blockIdx.x * 128;
    const int n0 = blockIdx.y * 128;

    const int lrA = (lane & 7) + ((lane >> 3) & 1) * 8;
    const int wA  = lane >> 4;
    const int lrB = (lane & 7) + ((lane >> 4) << 3);
    const int wB  = (lane >> 3) & 1;
    const int gid = lane >> 2, tig = lane & 3;

    float c[2][8][4];
#pragma unroll
    for (int i = 0; i < 2; i++)
#pragma unroll
        for (int j = 0; j < 8; j++)
#pragma unroll
            for (int q = 0; q < 4; q++) c[i][j][q] = 0.f;

    const int nkb = (K + 31) >> 5;

    // 1536 16B chunks per stage -> 6 per thread
    auto load_stage = [&](int stage, int k0) {
        const uint32_t stg = base + (uint32_t)stage * STAGE_B;
#pragma unroll
        for (int i = 0; i < 6; i++) {
            int idx = tid + i * 256;
            int ch = idx & 3;
            int r  = (idx >> 2) & 127;
            int t3 = idx >> 9;                  // 0:A 1:Bh 2:Bl
            uint32_t dst = stg + (uint32_t)t3 * TILE_B + (uint32_t)(r * ROWB + ch * 16);
            int ke = k0 + ch * 8;
            const half_t* sp;
            bool v;
            if (t3 == 0) {
                v = (m0 + r < M) && (ke < K);
                int rr = (m0 + r < M) ? (m0 + r) : 0;
                sp = A + (size_t)rr * K + ke;
            } else {
                v = (n0 + r < N) && (ke < K);
                const half_t* pb = (t3 == 1) ? Whi : Wlo;
                int rr = (n0 + r < N) ? (n0 + r) : 0;
                sp = pb + (size_t)rr * K + ke;
            }
            cp16(dst, sp, v);
        }
    };

    load_stage(0, 0);
    CP_COMMIT();

    for (int kb = 0; kb < nkb; kb++) {
        if (kb + 1 < nkb) load_stage((kb + 1) & 1, (kb + 1) << 5);
        CP_COMMIT();
        CP_WAIT1();
        __syncthreads();

        const uint32_t stg = base + (uint32_t)(kb & 1) * STAGE_B;
        const uint32_t sA = stg, sBh = stg + TILE_B, sBl = stg + 2 * TILE_B;

#pragma unroll
        for (int kc = 0; kc < 2; kc++) {
            const uint32_t acol = (uint32_t)((2 * kc + wA) * 16);
            const uint32_t bcol = (uint32_t)((2 * kc + wB) * 16);
            uint32_t a[2][4];
#pragma unroll
            for (int mt = 0; mt < 2; mt++) {
                uint32_t ro = (uint32_t)((wm * 32 + mt * 16 + lrA) * ROWB);
                ldsm_x4(a[mt][0], a[mt][1], a[mt][2], a[mt][3], sA + ro + acol);
            }
            uint32_t b[4][4];
#pragma unroll
            for (int nt = 0; nt < 4; nt++) {
                uint32_t ro = (uint32_t)((wn * 64 + nt * 16 + lrB) * ROWB);
                ldsm_x4(b[nt][0], b[nt][1], b[nt][2], b[nt][3], sBh + ro + bcol);
            }
#pragma unroll
            for (int mt = 0; mt < 2; mt++)
#pragma unroll
                for (int nt = 0; nt < 8; nt++) {
                    const int nn = nt >> 1, oc = (nt & 1) * 2;
                    mma_f16(c[mt][nt], a[mt], b[nn][oc], b[nn][oc + 1]);
                }
#pragma unroll
            for (int nt = 0; nt < 4; nt++) {
                uint32_t ro = (uint32_t)((wn * 64 + nt * 16 + lrB) * ROWB);
                ldsm_x4(b[nt][0], b[nt][1], b[nt][2], b[nt][3], sBl + ro + bcol);
            }
#pragma unroll
            for (int mt = 0; mt < 2; mt++)
#pragma unroll
                for (int nt = 0; nt < 8; nt++) {
                    const int nn = nt >> 1, oc = (nt & 1) * 2;
                    mma_f16(c[mt][nt], a[mt], b[nn][oc], b[nn][oc + 1]);
                }
        }
        __syncthreads();
    }

    // epilogue
#pragma unroll
    for (int nt = 0; nt < 8; nt++) {
        const int col = n0 + wn * 64 + nt * 8 + tig * 2;
        if (col >= N) continue;
        float2 bb = make_float2(0.f, 0.f);
        if (hbias) bb = *(const float2*)(bias + col);
#pragma unroll
        for (int mt = 0; mt < 2; mt++) {
            const int r0 = m0 + wm * 32 + mt * 16 + gid;
            float v0 = c[mt][nt][0] + bb.x, v1 = c[mt][nt][1] + bb.y;
            float v2 = c[mt][nt][2] + bb.x, v3 = c[mt][nt][3] + bb.y;
            if (relu) {
                v0 = fmaxf(v0, 0.f); v1 = fmaxf(v1, 0.f);
                v2 = fmaxf(v2, 0.f); v3 = fmaxf(v3, 0.f);
            }
            if (r0 < M) {
                size_t o = (size_t)r0 * N + col;
                if (wf32) *(float2*)(C + o) = make_float2(v0, v1);
                if (wf16) *(uint32_t*)(Ch + o) = pack_h2(v0, v1);
            }
            if (r0 + 8 < M) {
                size_t o = (size_t)(r0 + 8) * N + col;
                if (wf32) *(float2*)(C + o) = make_float2(v2, v3);
                if (wf16) *(uint32_t*)(Ch + o) = pack_h2(v2, v3);
            }
        }
    }
}

// ---------------- conversion / elementwise kernels ----------------
__global__ void conv_h(const float4* __restrict__ src, uint32_t* __restrict__ dst, size_t n4)
{
    size_t t = (size_t)blockIdx.x * blockDim.x + threadIdx.x;
    if (t >= n4) return;
    float4 v = src[t];
    dst[t * 2]     = pack_h2(v.x, v.y);
    dst[t * 2 + 1] = pack_h2(v.z, v.w);
}

__global__ void conv_w_hilo(const float* __restrict__ src, int lds,
                            half_t* __restrict__ hi, half_t* __restrict__ lo, int N, int K)
{
    int t = blockIdx.x * blockDim.x + threadIdx.x;
    if (t >= N * K) return;
    int r = t / K, cc = t % K;
    float v = src[(size_t)r * lds + cc];
    half_t h = __float2half_rn(v);
    hi[t] = h;
    lo[t] = __float2half_rn(v - __half2float(h));
}

__global__ void combine_wpi_hilo(const float* __restrict__ Wpi,
                                 half_t* __restrict__ hi, half_t* __restrict__ lo)
{
    int t = blockIdx.x * blockDim.x + threadIdx.x;
    if (t >= EMB * EMB) return;
    int r = t / EMB, cc = t % EMB;
    float v = Wpi[r * 600 + cc] + Wpi[r * 600 + 400 + cc];
    half_t h = __float2half_rn(v);
    hi[t] = h;
    lo[t] = __float2half_rn(v - __half2float(h));
}

__global__ void gather_rows_f4(const float* __restrict__ src, const int* __restrict__ idx,
                               float* __restrict__ dst, int nrows)
{
    const int C4 = EMB / 4;
    int t = blockIdx.x * blockDim.x + threadIdx.x;
    if (t >= nrows * C4) return;
    int r = t / C4, cc = t % C4;
    ((float4*)dst)[t] = ((const float4*)src)[(size_t)idx[r] * C4 + cc];
}

// pred_af = relu(tmpP + Acomb[sub] + bpi) -> fp16
__global__ void fuse_pi_h(const float* __restrict__ tmpP, const float* __restrict__ Acomb,
                          const int* __restrict__ rel_inds, const float* __restrict__ bias,
                          uint32_t* __restrict__ outh)
{
    const int C4 = EMB / 4;
    int t = blockIdx.x * blockDim.x + threadIdx.x;
    if (t >= N_REL * C4) return;
    int r = t / C4, cc = t % C4;
    int s = rel_inds[r * 3 + 1];
    float4 p = ((const float4*)tmpP)[t];
    float4 a = ((const float4*)Acomb)[(size_t)s * C4 + cc];
    float4 b = ((const float4*)bias)[cc];
    float v0 = fmaxf(p.x + a.x + b.x, 0.f), v1 = fmaxf(p.y + a.y + b.y, 0.f);
    float v2 = fmaxf(p.z + a.z + b.z, 0.f), v3 = fmaxf(p.w + a.w + b.w, 0.f);
    outh[t * 2]     = pack_h2(v0, v1);
    outh[t * 2 + 1] = pack_h2(v2, v3);
}

// hpo = relu(tmpQ + Bs[sub] + Bo[obj] + bpo1) -> fp16
__global__ void fuse_po_h(const float* __restrict__ tmpQ, const float* __restrict__ Bsub,
                          const float* __restrict__ Bobj, const int* __restrict__ rel_inds,
                          const float* __restrict__ bias, uint32_t* __restrict__ outh)
{
    const int C4 = EMB / 4;
    int t = blockIdx.x * blockDim.x + threadIdx.x;
    if (t >= N_REL * C4) return;
    int r = t / C4, cc = t % C4;
    int s = rel_inds[r * 3 + 1];
    int o = rel_inds[r * 3 + 2];
    float4 q  = ((const float4*)tmpQ)[t];
    float4 bs = ((const float4*)Bsub)[(size_t)s * C4 + cc];
    float4 bo = ((const float4*)Bobj)[(size_t)o * C4 + cc];
    float4 b  = ((const float4*)bias)[cc];
    float v0 = fmaxf(q.x + bs.x + bo.x + b.x, 0.f), v1 = fmaxf(q.y + bs.y + bo.y + b.y, 0.f);
    float v2 = fmaxf(q.z + bs.z + bo.z + b.z, 0.f), v3 = fmaxf(q.w + bs.w + bo.w + b.w, 0.f);
    outh[t * 2]     = pack_h2(v0, v1);
    outh[t * 2 + 1] = pack_h2(v2, v3);
}

// ---------------- host side ----------------
template <typename T>
static T* sym(const void* s)
{
    void* p = nullptr;
    cudaGetSymbolAddress(&p, s);
    return (T*)p;
}

static void gemmh(const half_t* A, const half_t* Whi, const half_t* Wlo,
                  const float* bias, float* C, half_t* Ch,
                  int M, int N, int K, bool relu)
{
    static bool attr_set = false;
    if (!attr_set) {
        cudaFuncSetAttribute(hmma_h, cudaFuncAttributeMaxDynamicSharedMemorySize, SMEM_TOT);
        attr_set = true;
    }
    dim3 grid((M + 127) / 128, (N + 127) / 128), block(256);
    hmma_h<<<grid, block, SMEM_TOT>>>(A, Whi, Wlo, bias, C, Ch, M, N, K,
                                      relu ? 1 : 0, C ? 1 : 0, Ch ? 1 : 0, bias ? 1 : 0);
}

static void convw(const float* src, int lds, half_t* hi, half_t* lo, int N, int K)
{
    int n = N * K;
    conv_w_hilo<<<(n + 255) / 256, 256>>>(src, lds, hi, lo, N, K);
}

extern "C" void kernel_launch(void* const* d_in, const int* in_sizes, int n_in,
                              void* d_out, int out_size)
{
    (void)in_sizes; (void)n_in; (void)out_size;

    const float* obj_feats  = (const float*)d_in[1];
    const float* rel_feats  = (const float*)d_in[2];
    const int*   rel_inds   = (const int*)d_in[4];
    const int*   gt_rel     = (const int*)d_in[5];
    const int*   gt_obj     = (const int*)d_in[6];
    const float* obj_embed  = (const float*)d_in[7];
    const float* pred_embed = (const float*)d_in[8];
    const float* Wrs = (const float*)d_in[9];  const float* brs = (const float*)d_in[10];
    const float* Wos = (const float*)d_in[11]; const float* bos = (const float*)d_in[12];
    const float* Wso1= (const float*)d_in[13]; const float* bso1= (const float*)d_in[14];
    const float* Wso2= (const float*)d_in[15]; const float* bso2= (const float*)d_in[16];
    const float* Wsoo= (const float*)d_in[17]; const float* bsoo= (const float*)d_in[18];
    const float* Wp1 = (const float*)d_in[19]; const float* bp1 = (const float*)d_in[20];
    const float* Wp2 = (const float*)d_in[21]; const float* bp2 = (const float*)d_in[22];
    const float* Wpi = (const float*)d_in[23]; const float* bpi = (const float*)d_in[24];
    const float* Wpo1= (const float*)d_in[25]; const float* bpo1= (const float*)d_in[26];
    const float* Wpo2= (const float*)d_in[27]; const float* bpo2= (const float*)d_in[28];

    float* out = (float*)d_out;
    float* o_so_out   = out;                      // [50000,200]
    float* o_pred_out = out + 10000000;           // [200000,200]
    float* o_rel_sem  = out + 50000000;           // [200000,200]
    float* o_obj_sem  = out + 90000000;           // [50000,200]
    float* o_rel_gt   = out + 100000000;          // [51,200]
    float* o_obj_gt   = out + 100010200;          // [151,200]

    half_t *frel = sym<half_t>(g_frel_h), *fobj = sym<half_t>(g_fobj_h);
    half_t *h1r = sym<half_t>(g_h1r_h), *h1o = sym<half_t>(g_h1o_h);
    half_t *pri = sym<half_t>(g_pri_h), *soi = sym<half_t>(g_soi_h);
    half_t *paf = sym<half_t>(g_paf_h), *soo = sym<half_t>(g_soo_h);
    half_t *hpo = sym<half_t>(g_hpo_h);
    half_t *pe = sym<half_t>(g_pe_h), *oe = sym<half_t>(g_oe_h);
    half_t *wrs_hi = sym<half_t>(g_wrs_hi), *wrs_lo = sym<half_t>(g_wrs_lo);
    half_t *wos_hi = sym<half_t>(g_wos_hi), *wos_lo = sym<half_t>(g_wos_lo);
    half_t *wso1_hi= sym<half_t>(g_wso1_hi),*wso1_lo= sym<half_t>(g_wso1_lo);
    half_t *wso2_hi= sym<half_t>(g_wso2_hi),*wso2_lo= sym<half_t>(g_wso2_lo);
    half_t *wsoo_hi= sym<half_t>(g_wsoo_hi),*wsoo_lo= sym<half_t>(g_wsoo_lo);
    half_t *wp1_hi = sym<half_t>(g_wp1_hi), *wp1_lo = sym<half_t>(g_wp1_lo);
    half_t *wp2_hi = sym<half_t>(g_wp2_hi), *wp2_lo = sym<half_t>(g_wp2_lo);
    half_t *wpip_hi= sym<half_t>(g_wpip_hi),*wpip_lo= sym<half_t>(g_wpip_lo);
    half_t *wcmb_hi= sym<half_t>(g_wcmb_hi),*wcmb_lo= sym<half_t>(g_wcmb_lo);
    half_t *w1s_hi = sym<half_t>(g_w1s_hi), *w1s_lo = sym<half_t>(g_w1s_lo);
    half_t *w1p_hi = sym<half_t>(g_w1p_hi), *w1p_lo = sym<half_t>(g_w1p_lo);
    half_t *w1o_hi = sym<half_t>(g_w1o_hi), *w1o_lo = sym<half_t>(g_w1o_lo);
    half_t *wpo2_hi= sym<half_t>(g_wpo2_hi),*wpo2_lo= sym<half_t>(g_wpo2_lo);
    float *Acomb = sym<float>(g_Acomb), *tmpP = sym<float>(g_tmpP);
    float *Bs = sym<float>(g_Bs), *Bo = sym<float>(g_Bo), *tmpQ = sym<float>(g_tmpQ);

    // ---- conversions ----
    {
        size_t n4 = (size_t)N_REL * FEAT / 4;
        conv_h<<<(int)((n4 + 255) / 256), 256>>>((const float4*)rel_feats, (uint32_t*)frel, n4);
        n4 = (size_t)N_OBJ * FEAT / 4;
        conv_h<<<(int)((n4 + 255) / 256), 256>>>((const float4*)obj_feats, (uint32_t*)fobj, n4);
        n4 = (size_t)N_PRED * EMB / 4;
        conv_h<<<(int)((n4 + 255) / 256), 256>>>((const float4*)pred_embed, (uint32_t*)pe, n4);
        n4 = (size_t)N_CLS * EMB / 4;
        conv_h<<<(int)((n4 + 255) / 256), 256>>>((const float4*)obj_embed, (uint32_t*)oe, n4);
    }
    convw(Wrs, EMB, wrs_hi, wrs_lo, EMB, EMB);
    convw(Wos, EMB, wos_hi, wos_lo, EMB, EMB);
    convw(Wso1, FEAT, wso1_hi, wso1_lo, INTER, FEAT);
    convw(Wso2, INTER, wso2_hi, wso2_lo, EMB, INTER);
    convw(Wsoo, EMB, wsoo_hi, wsoo_lo, EMB, EMB);
    convw(Wp1, FEAT, wp1_hi, wp1_lo, INTER, FEAT);
    convw(Wp2, INTER, wp2_hi, wp2_lo, EMB, INTER);
    convw(Wpi + EMB, 600, wpip_hi, wpip_lo, EMB, EMB);
    convw(Wpo1, 600, w1s_hi, w1s_lo, EMB, EMB);
    convw(Wpo1 + EMB, 600, w1p_hi, w1p_lo, EMB, EMB);
    convw(Wpo1 + 2 * EMB, 600, w1o_hi, w1o_lo, EMB, EMB);
    convw(Wpo2, EMB, wpo2_hi, wpo2_lo, EMB, EMB);
    combine_wpi_hilo<<<(EMB * EMB + 255) / 256, 256>>>(Wpi, wcmb_hi, wcmb_lo);

    // ---- semantic tables + gathers ----
    gemmh(pe, wrs_hi, wrs_lo, brs, o_rel_gt, nullptr, N_PRED, EMB, EMB, false);
    gemmh(oe, wos_hi, wos_lo, bos, o_obj_gt, nullptr, N_CLS, EMB, EMB, false);
    gather_rows_f4<<<(N_REL * (EMB / 4) + 255) / 256, 256>>>(o_rel_gt, gt_rel, o_rel_sem, N_REL);
    gather_rows_f4<<<(N_OBJ * (EMB / 4) + 255) / 256, 256>>>(o_obj_gt, gt_obj, o_obj_sem, N_OBJ);

    // ---- object path ----
    gemmh(fobj, wso1_hi, wso1_lo, bso1, nullptr, h1o, N_OBJ, INTER, FEAT, true);
    gemmh(h1o, wso2_hi, wso2_lo, bso2, nullptr, soi, N_OBJ, EMB, INTER, true);
    gemmh(soi, wsoo_hi, wsoo_lo, bsoo, o_so_out, soo, N_OBJ, EMB, EMB, false);

    // ---- relation path ----
    gemmh(frel, wp1_hi, wp1_lo, bp1, nullptr, h1r, N_REL, INTER, FEAT, true);
    gemmh(h1r, wp2_hi, wp2_lo, bp2, nullptr, pri, N_REL, EMB, INTER, true);

    // ---- pred_inter_af (factored concat; obj slice == sub slice index) ----
    gemmh(soi, wcmb_hi, wcmb_lo, nullptr, Acomb, nullptr, N_OBJ, EMB, EMB, false);
    gemmh(pri, wpip_hi, wpip_lo, nullptr, tmpP, nullptr, N_REL, EMB, EMB, false);
    fuse_pi_h<<<(N_REL * (EMB / 4) + 255) / 256, 256>>>(tmpP, Acomb, rel_inds, bpi,
                                                        (uint32_t*)paf);

    // ---- pred_out (factored concat) ----
    gemmh(soo, w1s_hi, w1s_lo, nullptr, Bs, nullptr, N_OBJ, EMB, EMB, false);
    gemmh(soo, w1o_hi, w1o_lo, nullptr, Bo, nullptr, N_OBJ, EMB, EMB, false);
    gemmh(paf, w1p_hi, w1p_lo, nullptr, tmpQ, nullptr, N_REL, EMB, EMB, false);
    fuse_po_h<<<(N_REL * (EMB / 4) + 255) / 256, 256>>>(tmpQ, Bs, Bo, rel_inds, bpo1,
                                                        (uint32_t*)hpo);
    gemmh(hpo, wpo2_hi, wpo2_lo, bpo2, o_pred_out, nullptr, N_REL, EMB, EMB, false);
}

// round 6
// speedup vs baseline: 2.5470x; 1.5363x over previous
#include <cuda_runtime.h>
#include <cuda_fp16.h>
#include <cstdint>
#include <cstring>

#define N_OBJ 50000
#define N_REL 200000
#define FEAT 1024
#define INTER 512
#define EMB 200
#define N_CLS 151
#define N_PRED 51

typedef __half half_t;

// ---------------- scratch ----------------
// fp16 activations
__device__ half_t g_frel_h[(size_t)N_REL * FEAT];
__device__ half_t g_fobj_h[(size_t)N_OBJ * FEAT];
__device__ half_t g_h1r_h[(size_t)N_REL * INTER];
__device__ half_t g_h1o_h[(size_t)N_OBJ * INTER];
__device__ half_t g_pri_h[(size_t)N_REL * EMB];
__device__ half_t g_soi_h[(size_t)N_OBJ * EMB];
__device__ half_t g_paf_h[(size_t)N_REL * EMB];
__device__ half_t g_soo_h[(size_t)N_OBJ * EMB];
__device__ half_t g_hpo_h[(size_t)N_REL * EMB];
__device__ half_t g_pe_h[N_PRED * EMB];
__device__ half_t g_oe_h[N_CLS * EMB];
// fp16 weights (single precision)
__device__ half_t g_wrs[EMB * EMB];
__device__ half_t g_wos[EMB * EMB];
__device__ half_t g_wso1[INTER * FEAT];
__device__ half_t g_wso2[EMB * INTER];
__device__ half_t g_wsoo[EMB * EMB];
__device__ half_t g_wp1[INTER * FEAT];
__device__ half_t g_wp2[EMB * INTER];
__device__ half_t g_wpip[EMB * EMB];
__device__ half_t g_wcmb[EMB * EMB];
__device__ half_t g_w1s[EMB * EMB];
__device__ half_t g_w1p[EMB * EMB];
__device__ half_t g_w1o[EMB * EMB];
__device__ half_t g_wpo2[EMB * EMB];
// fp32 intermediates
__device__ float g_Acomb[(size_t)N_OBJ * EMB];
__device__ float g_tmpP[(size_t)N_REL * EMB];
__device__ float g_Bs[(size_t)N_OBJ * EMB];
__device__ float g_Bo[(size_t)N_OBJ * EMB];
__device__ float g_tmpQ[(size_t)N_REL * EMB];

// ---------------- device helpers ----------------
__device__ __forceinline__ uint32_t smem_u32(const void* p) {
    uint32_t a;
    asm("{ .reg .u64 t; cvta.to.shared.u64 t, %1; cvt.u32.u64 %0, t; }" : "=r"(a) : "l"(p));
    return a;
}

__device__ __forceinline__ void ldsm_x4(uint32_t& r0, uint32_t& r1, uint32_t& r2, uint32_t& r3,
                                        uint32_t addr) {
    asm volatile("ldmatrix.sync.aligned.m8n8.x4.shared.b16 {%0,%1,%2,%3}, [%4];"
                 : "=r"(r0), "=r"(r1), "=r"(r2), "=r"(r3) : "r"(addr));
}

__device__ __forceinline__ void mma_f16(float* c, const uint32_t* a, uint32_t b0, uint32_t b1) {
    asm volatile("mma.sync.aligned.m16n8k16.row.col.f32.f16.f16.f32 "
                 "{%0,%1,%2,%3}, {%4,%5,%6,%7}, {%8,%9}, {%0,%1,%2,%3};"
                 : "+f"(c[0]), "+f"(c[1]), "+f"(c[2]), "+f"(c[3])
                 : "r"(a[0]), "r"(a[1]), "r"(a[2]), "r"(a[3]), "r"(b0), "r"(b1));
}

__device__ __forceinline__ void cp16(uint32_t dst, const void* src, bool valid) {
    int sz = valid ? 16 : 0;
    asm volatile("cp.async.cg.shared.global [%0], [%1], 16, %2;"
                 :: "r"(dst), "l"(src), "r"(sz) : "memory");
}
#define CP_COMMIT() asm volatile("cp.async.commit_group;" ::: "memory")
#define CP_WAIT1()  asm volatile("cp.async.wait_group 1;" ::: "memory")

__device__ __forceinline__ uint32_t pack_h2(float x, float y) {
    __half2 h = __floats2half2_rn(x, y);
    uint32_t u; memcpy(&u, &h, 4); return u;
}

// ---------------- fp16 single-pass GEMM: C = act(A @ W^T + bias) ----------
// CTA 128x128, BK=32, 8 warps (4M x 2N), warp tile 32x64
#define ROWB 80
#define TILE_B (128 * ROWB)      // 10240
#define STAGE_B (2 * TILE_B)     // A, B
#define SMEM_TOT (2 * STAGE_B)   // 40960

__global__ __launch_bounds__(256, 2)
void hmma_h(const half_t* __restrict__ A, const half_t* __restrict__ W,
            const float* __restrict__ bias,
            float* __restrict__ C, half_t* __restrict__ Ch,
            int M, int N, int K, int relu, int wf32, int wf16, int hbias)
{
    extern __shared__ __align__(16) char smem[];
    const uint32_t base = smem_u32(smem);

    const int tid = threadIdx.x;
    const int lane = tid & 31;
    const int wid = tid >> 5;
    const int wm = wid & 3;
    const int wn = wid >> 2;
    const int m0 = blockIdx.x * 128;
    const int n0 = blockIdx.y * 128;

    const int lrA = (lane & 7) + ((lane >> 3) & 1) * 8;
    const int wA  = lane >> 4;
    const int lrB = (lane & 7) + ((lane >> 4) << 3);
    const int wB  = (lane >> 3) & 1;
    const int gid = lane >> 2, tig = lane & 3;

    float c[2][8][4];
#pragma unroll
    for (int i = 0; i < 2; i++)
#pragma unroll
        for (int j = 0; j < 8; j++)
#pragma unroll
            for (int q = 0; q < 4; q++) c[i][j][q] = 0.f;

    const int nkb = (K + 31) >> 5;

    // 1024 16B chunks per stage -> 4 per thread
    auto load_stage = [&](int stage, int k0) {
        const uint32_t stg = base + (uint32_t)stage * STAGE_B;
#pragma unroll
        for (int i = 0; i < 4; i++) {
            int idx = tid + i * 256;
            int ch = idx & 3;
            int r  = (idx >> 2) & 127;
            int t2 = idx >> 9;                  // 0:A 1:B
            uint32_t dst = stg + (uint32_t)t2 * TILE_B + (uint32_t)(r * ROWB + ch * 16);
            int ke = k0 + ch * 8;
            const half_t* sp;
            bool v;
            if (t2 == 0) {
                v = (m0 + r < M) && (ke < K);
                int rr = (m0 + r < M) ? (m0 + r) : 0;
                sp = A + (size_t)rr * K + ke;
            } else {
                v = (n0 + r < N) && (ke < K);
                int rr = (n0 + r < N) ? (n0 + r) : 0;
                sp = W + (size_t)rr * K + ke;
            }
            cp16(dst, sp, v);
        }
    };

    load_stage(0, 0);
    CP_COMMIT();

    for (int kb = 0; kb < nkb; kb++) {
        if (kb + 1 < nkb) load_stage((kb + 1) & 1, (kb + 1) << 5);
        CP_COMMIT();
        CP_WAIT1();
        __syncthreads();

        const uint32_t stg = base + (uint32_t)(kb & 1) * STAGE_B;
        const uint32_t sA = stg, sB = stg + TILE_B;

#pragma unroll
        for (int kc = 0; kc < 2; kc++) {
            const uint32_t acol = (uint32_t)((2 * kc + wA) * 16);
            const uint32_t bcol = (uint32_t)((2 * kc + wB) * 16);
            uint32_t a[2][4];
#pragma unroll
            for (int mt = 0; mt < 2; mt++) {
                uint32_t ro = (uint32_t)((wm * 32 + mt * 16 + lrA) * ROWB);
                ldsm_x4(a[mt][0], a[mt][1], a[mt][2], a[mt][3], sA + ro + acol);
            }
            uint32_t b[4][4];
#pragma unroll
            for (int nt = 0; nt < 4; nt++) {
                uint32_t ro = (uint32_t)((wn * 64 + nt * 16 + lrB) * ROWB);
                ldsm_x4(b[nt][0], b[nt][1], b[nt][2], b[nt][3], sB + ro + bcol);
            }
#pragma unroll
            for (int mt = 0; mt < 2; mt++)
#pragma unroll
                for (int nt = 0; nt < 8; nt++) {
                    const int nn = nt >> 1, oc = (nt & 1) * 2;
                    mma_f16(c[mt][nt], a[mt], b[nn][oc], b[nn][oc + 1]);
                }
        }
        __syncthreads();
    }

    // epilogue
#pragma unroll
    for (int nt = 0; nt < 8; nt++) {
        const int col = n0 + wn * 64 + nt * 8 + tig * 2;
        if (col >= N) continue;
        float2 bb = make_float2(0.f, 0.f);
        if (hbias) bb = *(const float2*)(bias + col);
#pragma unroll
        for (int mt = 0; mt < 2; mt++) {
            const int r0 = m0 + wm * 32 + mt * 16 + gid;
            float v0 = c[mt][nt][0] + bb.x, v1 = c[mt][nt][1] + bb.y;
            float v2 = c[mt][nt][2] + bb.x, v3 = c[mt][nt][3] + bb.y;
            if (relu) {
                v0 = fmaxf(v0, 0.f); v1 = fmaxf(v1, 0.f);
                v2 = fmaxf(v2, 0.f); v3 = fmaxf(v3, 0.f);
            }
            if (r0 < M) {
                size_t o = (size_t)r0 * N + col;
                if (wf32) *(float2*)(C + o) = make_float2(v0, v1);
                if (wf16) *(uint32_t*)(Ch + o) = pack_h2(v0, v1);
            }
            if (r0 + 8 < M) {
                size_t o = (size_t)(r0 + 8) * N + col;
                if (wf32) *(float2*)(C + o) = make_float2(v2, v3);
                if (wf16) *(uint32_t*)(Ch + o) = pack_h2(v2, v3);
            }
        }
    }
}

// ---------------- conversion / elementwise kernels ----------------
__global__ void conv_h(const float4* __restrict__ src, uint32_t* __restrict__ dst, size_t n4)
{
    size_t t = (size_t)blockIdx.x * blockDim.x + threadIdx.x;
    if (t >= n4) return;
    float4 v = src[t];
    dst[t * 2]     = pack_h2(v.x, v.y);
    dst[t * 2 + 1] = pack_h2(v.z, v.w);
}

__global__ void conv_w(const float* __restrict__ src, int lds,
                       half_t* __restrict__ dst, int N, int K)
{
    int t = blockIdx.x * blockDim.x + threadIdx.x;
    if (t >= N * K) return;
    int r = t / K, cc = t % K;
    dst[t] = __float2half_rn(src[(size_t)r * lds + cc]);
}

__global__ void combine_wpi_h(const float* __restrict__ Wpi, half_t* __restrict__ dst)
{
    int t = blockIdx.x * blockDim.x + threadIdx.x;
    if (t >= EMB * EMB) return;
    int r = t / EMB, cc = t % EMB;
    dst[t] = __float2half_rn(Wpi[r * 600 + cc] + Wpi[r * 600 + 400 + cc]);
}

__global__ void gather_rows_f4(const float* __restrict__ src, const int* __restrict__ idx,
                               float* __restrict__ dst, int nrows)
{
    const int C4 = EMB / 4;
    int t = blockIdx.x * blockDim.x + threadIdx.x;
    if (t >= nrows * C4) return;
    int r = t / C4, cc = t % C4;
    ((float4*)dst)[t] = ((const float4*)src)[(size_t)idx[r] * C4 + cc];
}

// pred_af = relu(tmpP + Acomb[sub] + bpi) -> fp16
__global__ void fuse_pi_h(const float* __restrict__ tmpP, const float* __restrict__ Acomb,
                          const int* __restrict__ rel_inds, const float* __restrict__ bias,
                          uint32_t* __restrict__ outh)
{
    const int C4 = EMB / 4;
    int t = blockIdx.x * blockDim.x + threadIdx.x;
    if (t >= N_REL * C4) return;
    int r = t / C4, cc = t % C4;
    int s = rel_inds[r * 3 + 1];
    float4 p = ((const float4*)tmpP)[t];
    float4 a = ((const float4*)Acomb)[(size_t)s * C4 + cc];
    float4 b = ((const float4*)bias)[cc];
    float v0 = fmaxf(p.x + a.x + b.x, 0.f), v1 = fmaxf(p.y + a.y + b.y, 0.f);
    float v2 = fmaxf(p.z + a.z + b.z, 0.f), v3 = fmaxf(p.w + a.w + b.w, 0.f);
    outh[t * 2]     = pack_h2(v0, v1);
    outh[t * 2 + 1] = pack_h2(v2, v3);
}

// hpo = relu(tmpQ + Bs[sub] + Bo[obj] + bpo1) -> fp16
__global__ void fuse_po_h(const float* __restrict__ tmpQ, const float* __restrict__ Bsub,
                          const float* __restrict__ Bobj, const int* __restrict__ rel_inds,
                          const float* __restrict__ bias, uint32_t* __restrict__ outh)
{
    const int C4 = EMB / 4;
    int t = blockIdx.x * blockDim.x + threadIdx.x;
    if (t >= N_REL * C4) return;
    int r = t / C4, cc = t % C4;
    int s = rel_inds[r * 3 + 1];
    int o = rel_inds[r * 3 + 2];
    float4 q  = ((const float4*)tmpQ)[t];
    float4 bs = ((const float4*)Bsub)[(size_t)s * C4 + cc];
    float4 bo = ((const float4*)Bobj)[(size_t)o * C4 + cc];
    float4 b  = ((const float4*)bias)[cc];
    float v0 = fmaxf(q.x + bs.x + bo.x + b.x, 0.f), v1 = fmaxf(q.y + bs.y + bo.y + b.y, 0.f);
    float v2 = fmaxf(q.z + bs.z + bo.z + b.z, 0.f), v3 = fmaxf(q.w + bs.w + bo.w + b.w, 0.f);
    outh[t * 2]     = pack_h2(v0, v1);
    outh[t * 2 + 1] = pack_h2(v2, v3);
}

// ---------------- host side ----------------
template <typename T>
static T* sym(const void* s)
{
    void* p = nullptr;
    cudaGetSymbolAddress(&p, s);
    return (T*)p;
}

static void gemmh(const half_t* A, const half_t* W, const float* bias,
                  float* C, half_t* Ch, int M, int N, int K, bool relu)
{
    static bool attr_set = false;
    if (!attr_set) {
        cudaFuncSetAttribute(hmma_h, cudaFuncAttributeMaxDynamicSharedMemorySize, SMEM_TOT);
        attr_set = true;
    }
    dim3 grid((M + 127) / 128, (N + 127) / 128), block(256);
    hmma_h<<<grid, block, SMEM_TOT>>>(A, W, bias, C, Ch, M, N, K,
                                      relu ? 1 : 0, C ? 1 : 0, Ch ? 1 : 0, bias ? 1 : 0);
}

static void convw(const float* src, int lds, half_t* dst, int N, int K)
{
    int n = N * K;
    conv_w<<<(n + 255) / 256, 256>>>(src, lds, dst, N, K);
}

extern "C" void kernel_launch(void* const* d_in, const int* in_sizes, int n_in,
                              void* d_out, int out_size)
{
    (void)in_sizes; (void)n_in; (void)out_size;

    const float* obj_feats  = (const float*)d_in[1];
    const float* rel_feats  = (const float*)d_in[2];
    const int*   rel_inds   = (const int*)d_in[4];
    const int*   gt_rel     = (const int*)d_in[5];
    const int*   gt_obj     = (const int*)d_in[6];
    const float* obj_embed  = (const float*)d_in[7];
    const float* pred_embed = (const float*)d_in[8];
    const float* Wrs = (const float*)d_in[9];  const float* brs = (const float*)d_in[10];
    const float* Wos = (const float*)d_in[11]; const float* bos = (const float*)d_in[12];
    const float* Wso1= (const float*)d_in[13]; const float* bso1= (const float*)d_in[14];
    const float* Wso2= (const float*)d_in[15]; const float* bso2= (const float*)d_in[16];
    const float* Wsoo= (const float*)d_in[17]; const float* bsoo= (const float*)d_in[18];
    const float* Wp1 = (const float*)d_in[19]; const float* bp1 = (const float*)d_in[20];
    const float* Wp2 = (const float*)d_in[21]; const float* bp2 = (const float*)d_in[22];
    const float* Wpi = (const float*)d_in[23]; const float* bpi = (const float*)d_in[24];
    const float* Wpo1= (const float*)d_in[25]; const float* bpo1= (const float*)d_in[26];
    const float* Wpo2= (const float*)d_in[27]; const float* bpo2= (const float*)d_in[28];

    float* out = (float*)d_out;
    float* o_so_out   = out;                      // [50000,200]
    float* o_pred_out = out + 10000000;           // [200000,200]
    float* o_rel_sem  = out + 50000000;           // [200000,200]
    float* o_obj_sem  = out + 90000000;           // [50000,200]
    float* o_rel_gt   = out + 100000000;          // [51,200]
    float* o_obj_gt   = out + 100010200;          // [151,200]

    half_t *frel = sym<half_t>(g_frel_h), *fobj = sym<half_t>(g_fobj_h);
    half_t *h1r = sym<half_t>(g_h1r_h), *h1o = sym<half_t>(g_h1o_h);
    half_t *pri = sym<half_t>(g_pri_h), *soi = sym<half_t>(g_soi_h);
    half_t *paf = sym<half_t>(g_paf_h), *soo = sym<half_t>(g_soo_h);
    half_t *hpo = sym<half_t>(g_hpo_h);
    half_t *pe = sym<half_t>(g_pe_h), *oe = sym<half_t>(g_oe_h);
    half_t *wrs = sym<half_t>(g_wrs), *wos = sym<half_t>(g_wos);
    half_t *wso1 = sym<half_t>(g_wso1), *wso2 = sym<half_t>(g_wso2);
    half_t *wsoo = sym<half_t>(g_wsoo);
    half_t *wp1 = sym<half_t>(g_wp1), *wp2 = sym<half_t>(g_wp2);
    half_t *wpip = sym<half_t>(g_wpip), *wcmb = sym<half_t>(g_wcmb);
    half_t *w1s = sym<half_t>(g_w1s), *w1p = sym<half_t>(g_w1p), *w1o = sym<half_t>(g_w1o);
    half_t *wpo2 = sym<half_t>(g_wpo2);
    float *Acomb = sym<float>(g_Acomb), *tmpP = sym<float>(g_tmpP);
    float *Bs = sym<float>(g_Bs), *Bo = sym<float>(g_Bo), *tmpQ = sym<float>(g_tmpQ);

    // ---- conversions ----
    {
        size_t n4 = (size_t)N_REL * FEAT / 4;
        conv_h<<<(int)((n4 + 255) / 256), 256>>>((const float4*)rel_feats, (uint32_t*)frel, n4);
        n4 = (size_t)N_OBJ * FEAT / 4;
        conv_h<<<(int)((n4 + 255) / 256), 256>>>((const float4*)obj_feats, (uint32_t*)fobj, n4);
        n4 = (size_t)N_PRED * EMB / 4;
        conv_h<<<(int)((n4 + 255) / 256), 256>>>((const float4*)pred_embed, (uint32_t*)pe, n4);
        n4 = (size_t)N_CLS * EMB / 4;
        conv_h<<<(int)((n4 + 255) / 256), 256>>>((const float4*)obj_embed, (uint32_t*)oe, n4);
    }
    convw(Wrs, EMB, wrs, EMB, EMB);
    convw(Wos, EMB, wos, EMB, EMB);
    convw(Wso1, FEAT, wso1, INTER, FEAT);
    convw(Wso2, INTER, wso2, EMB, INTER);
    convw(Wsoo, EMB, wsoo, EMB, EMB);
    convw(Wp1, FEAT, wp1, INTER, FEAT);
    convw(Wp2, INTER, wp2, EMB, INTER);
    convw(Wpi + EMB, 600, wpip, EMB, EMB);
    convw(Wpo1, 600, w1s, EMB, EMB);
    convw(Wpo1 + EMB, 600, w1p, EMB, EMB);
    convw(Wpo1 + 2 * EMB, 600, w1o, EMB, EMB);
    convw(Wpo2, EMB, wpo2, EMB, EMB);
    combine_wpi_h<<<(EMB * EMB + 255) / 256, 256>>>(Wpi, wcmb);

    // ---- semantic tables + gathers ----
    gemmh(pe, wrs, brs, o_rel_gt, nullptr, N_PRED, EMB, EMB, false);
    gemmh(oe, wos, bos, o_obj_gt, nullptr, N_CLS, EMB, EMB, false);
    gather_rows_f4<<<(N_REL * (EMB / 4) + 255) / 256, 256>>>(o_rel_gt, gt_rel, o_rel_sem, N_REL);
    gather_rows_f4<<<(N_OBJ * (EMB / 4) + 255) / 256, 256>>>(o_obj_gt, gt_obj, o_obj_sem, N_OBJ);

    // ---- object path ----
    gemmh(fobj, wso1, bso1, nullptr, h1o, N_OBJ, INTER, FEAT, true);
    gemmh(h1o, wso2, bso2, nullptr, soi, N_OBJ, EMB, INTER, true);
    gemmh(soi, wsoo, bsoo, o_so_out, soo, N_OBJ, EMB, EMB, false);

    // ---- relation path ----
    gemmh(frel, wp1, bp1, nullptr, h1r, N_REL, INTER, FEAT, true);
    gemmh(h1r, wp2, bp2, nullptr, pri, N_REL, EMB, INTER, true);

    // ---- pred_inter_af (factored concat; obj slice == sub slice index) ----
    gemmh(soi, wcmb, nullptr, Acomb, nullptr, N_OBJ, EMB, EMB, false);
    gemmh(pri, wpip, nullptr, tmpP, nullptr, N_REL, EMB, EMB, false);
    fuse_pi_h<<<(N_REL * (EMB / 4) + 255) / 256, 256>>>(tmpP, Acomb, rel_inds, bpi,
                                                        (uint32_t*)paf);

    // ---- pred_out (factored concat) ----
    gemmh(soo, w1s, nullptr, Bs, nullptr, N_OBJ, EMB, EMB, false);
    gemmh(soo, w1o, nullptr, Bo, nullptr, N_OBJ, EMB, EMB, false);
    gemmh(paf, w1p, nullptr, tmpQ, nullptr, N_REL, EMB, EMB, false);
    fuse_po_h<<<(N_REL * (EMB / 4) + 255) / 256, 256>>>(tmpQ, Bs, Bo, rel_inds, bpo1,
                                                        (uint32_t*)hpo);
    gemmh(hpo, wpo2, bpo2, o_pred_out, nullptr, N_REL, EMB, EMB, false);
}

// round 8
// speedup vs baseline: 2.7772x; 1.0904x over previous
#include <cuda_runtime.h>
#include <cuda_fp16.h>
#include <cstdint>
#include <cstring>

#define N_OBJ 50000
#define N_REL 200000
#define FEAT 1024
#define INTER 512
#define EMB 200
#define N_CLS 151
#define N_PRED 51

typedef __half half_t;

// ---------------- scratch ----------------
__device__ half_t g_h1r_h[(size_t)N_REL * INTER];
__device__ half_t g_h1o_h[(size_t)N_OBJ * INTER];
__device__ half_t g_pri_h[(size_t)N_REL * EMB];
__device__ half_t g_soi_h[(size_t)N_OBJ * EMB];
__device__ half_t g_paf_h[(size_t)N_REL * EMB];
__device__ half_t g_soo_h[(size_t)N_OBJ * EMB];
__device__ half_t g_hpo_h[(size_t)N_REL * EMB];
__device__ half_t g_pe_h[N_PRED * EMB];
__device__ half_t g_oe_h[N_CLS * EMB];
// fp16 weights
__device__ half_t g_wrs[EMB * EMB];
__device__ half_t g_wos[EMB * EMB];
__device__ half_t g_wso1[INTER * FEAT];
__device__ half_t g_wso2[EMB * INTER];
__device__ half_t g_wsoo[EMB * EMB];
__device__ half_t g_wp1[INTER * FEAT];
__device__ half_t g_wp2[EMB * INTER];
__device__ half_t g_wpip[EMB * EMB];
__device__ half_t g_wcmb[EMB * EMB];
__device__ half_t g_w1s[EMB * EMB];
__device__ half_t g_w1p[EMB * EMB];
__device__ half_t g_w1o[EMB * EMB];
__device__ half_t g_wpo2[EMB * EMB];
// fp32 intermediates
__device__ float g_Acomb[(size_t)N_OBJ * EMB];
__device__ float g_tmpP[(size_t)N_REL * EMB];
__device__ float g_Bs[(size_t)N_OBJ * EMB];
__device__ float g_Bo[(size_t)N_OBJ * EMB];
__device__ float g_tmpQ[(size_t)N_REL * EMB];

// ---------------- device helpers ----------------
__device__ __forceinline__ uint32_t smem_u32(const void* p) {
    uint32_t a;
    asm("{ .reg .u64 t; cvta.to.shared.u64 t, %1; cvt.u32.u64 %0, t; }" : "=r"(a) : "l"(p));
    return a;
}

__device__ __forceinline__ void ldsm_x4(uint32_t& r0, uint32_t& r1, uint32_t& r2, uint32_t& r3,
                                        uint32_t addr) {
    asm volatile("ldmatrix.sync.aligned.m8n8.x4.shared.b16 {%0,%1,%2,%3}, [%4];"
                 : "=r"(r0), "=r"(r1), "=r"(r2), "=r"(r3) : "r"(addr));
}

__device__ __forceinline__ void mma_f16(float* c, const uint32_t* a, uint32_t b0, uint32_t b1) {
    asm volatile("mma.sync.aligned.m16n8k16.row.col.f32.f16.f16.f32 "
                 "{%0,%1,%2,%3}, {%4,%5,%6,%7}, {%8,%9}, {%0,%1,%2,%3};"
                 : "+f"(c[0]), "+f"(c[1]), "+f"(c[2]), "+f"(c[3])
                 : "r"(a[0]), "r"(a[1]), "r"(a[2]), "r"(a[3]), "r"(b0), "r"(b1));
}

__device__ __forceinline__ void cp16(uint32_t dst, const void* src, bool valid) {
    int sz = valid ? 16 : 0;
    asm volatile("cp.async.cg.shared.global [%0], [%1], 16, %2;"
                 :: "r"(dst), "l"(src), "r"(sz) : "memory");
}
#define CP_COMMIT() asm volatile("cp.async.commit_group;" ::: "memory")
#define CP_WAIT1()  asm volatile("cp.async.wait_group 1;" ::: "memory")

__device__ __forceinline__ uint32_t pack_h2(float x, float y) {
    __half2 h = __floats2half2_rn(x, y);
    uint32_t u; memcpy(&u, &h, 4); return u;
}

// ---------------- fp16 GEMM: C = act(A @ W^T + bias) ----------
// CTA 128x128, BK=32, 8 warps (4M x 2N). AF32: A is fp32, converted on STS.
// grid: blockIdx.x = N-tile (fast), blockIdx.y = M-tile (L2 reuse of A).
#define ROWB 80
#define TILE_B (128 * ROWB)      // 10240
#define STAGE_B (2 * TILE_B)     // A, B
#define SMEM_TOT (2 * STAGE_B)   // 40960

template<int AF32>
__global__ __launch_bounds__(256, 2)
void hmma_h(const void* __restrict__ Av, const half_t* __restrict__ W,
            const float* __restrict__ bias,
            float* __restrict__ C, half_t* __restrict__ Ch,
            int M, int N, int K, int relu, int wf32, int wf16, int hbias)
{
    extern __shared__ __align__(16) char smem[];
    const uint32_t base = smem_u32(smem);

    const int tid = threadIdx.x;
    const int lane = tid & 31;
    const int wid = tid >> 5;
    const int wm = wid & 3;
    const int wn = wid >> 2;
    const int m0 = blockIdx.y * 128;
    const int n0 = blockIdx.x * 128;

    const int lrA = (lane & 7) + ((lane >> 3) & 1) * 8;
    const int wA  = lane >> 4;
    const int lrB = (lane & 7) + ((lane >> 4) << 3);
    const int wB  = (lane >> 3) & 1;
    const int gid = lane >> 2, tig = lane & 3;

    float c[2][8][4];
#pragma unroll
    for (int i = 0; i < 2; i++)
#pragma unroll
        for (int j = 0; j < 8; j++)
#pragma unroll
            for (int q = 0; q < 4; q++) c[i][j][q] = 0.f;

    const int nkb = (K + 31) >> 5;
    const float* A32 = (const float*)Av;
    const half_t* A16 = (const half_t*)Av;

    float4 ra[4];   // AF32 register prefetch buffer

    // fp32-A register prefetch: A tile 128x32 fp32 = 1024 float4 -> 4/thread
    auto prefetch_a32 = [&](int k0) {
#pragma unroll
        for (int i = 0; i < 4; i++) {
            int idx = tid + i * 256;
            int r = idx >> 3, c4 = idx & 7, gk = k0 + c4 * 4;
            bool v = (m0 + r < M) && (gk < K);
            int rr = (m0 + r < M) ? (m0 + r) : 0;
            ra[i] = v ? *(const float4*)(A32 + (size_t)rr * K + (gk < K ? gk : 0))
                      : make_float4(0.f, 0.f, 0.f, 0.f);
        }
    };
    auto sts_a32 = [&](int stage) {
        const uint32_t stg = base + (uint32_t)stage * STAGE_B;
#pragma unroll
        for (int i = 0; i < 4; i++) {
            int idx = tid + i * 256;
            int r = idx >> 3, c4 = idx & 7;
            uint32_t h0 = pack_h2(ra[i].x, ra[i].y);
            uint32_t h1 = pack_h2(ra[i].z, ra[i].w);
            uint32_t dst = stg + (uint32_t)(r * ROWB + c4 * 8);
            asm volatile("st.shared.v2.b32 [%0], {%1, %2};"
                         :: "r"(dst), "r"(h0), "r"(h1) : "memory");
        }
    };
    // W cp.async: 512 chunks -> 2/thread
    auto cp_w = [&](int stage, int k0) {
        const uint32_t stg = base + (uint32_t)stage * STAGE_B + TILE_B;
#pragma unroll
        for (int i = 0; i < 2; i++) {
            int idx = tid + i * 256;
            int ch = idx & 3, r = idx >> 2;
            uint32_t dst = stg + (uint32_t)(r * ROWB + ch * 16);
            int ke = k0 + ch * 8;
            bool v = (n0 + r < N) && (ke < K);              // ke<K: K=200 tail!
            int rr = (n0 + r < N) ? (n0 + r) : 0;
            cp16(dst, W + (size_t)rr * K + (ke < K ? ke : 0), v);
        }
    };
    // fp16 A+W cp.async: 1024 chunks -> 4/thread
    auto cp_aw16 = [&](int stage, int k0) {
        const uint32_t stg = base + (uint32_t)stage * STAGE_B;
#pragma unroll
        for (int i = 0; i < 4; i++) {
            int idx = tid + i * 256;
            int ch = idx & 3;
            int r  = (idx >> 2) & 127;
            int t2 = idx >> 9;
            uint32_t dst = stg + (uint32_t)t2 * TILE_B + (uint32_t)(r * ROWB + ch * 16);
            int ke = k0 + ch * 8;
            const half_t* sp;
            bool v;
            if (t2 == 0) {
                v = (m0 + r < M) && (ke < K);               // ke<K: K=200 tail!
                int rr = (m0 + r < M) ? (m0 + r) : 0;
                sp = A16 + (size_t)rr * K + (ke < K ? ke : 0);
            } else {
                v = (n0 + r < N) && (ke < K);
                int rr = (n0 + r < N) ? (n0 + r) : 0;
                sp = W + (size_t)rr * K + (ke < K ? ke : 0);
            }
            cp16(dst, sp, v);
        }
    };

    if (AF32) { prefetch_a32(0); cp_w(0, 0); }
    else      { cp_aw16(0, 0); }
    CP_COMMIT();

    for (int kb = 0; kb < nkb; kb++) {
        const int s = kb & 1;
        if (AF32) {
            if (kb + 1 < nkb) cp_w(s ^ 1, (kb + 1) << 5);
            CP_COMMIT();
            CP_WAIT1();
            sts_a32(s);
            __syncthreads();
            if (kb + 1 < nkb) prefetch_a32((kb + 1) << 5);   // overlaps MMA
        } else {
            if (kb + 1 < nkb) cp_aw16(s ^ 1, (kb + 1) << 5);
            CP_COMMIT();
            CP_WAIT1();
            __syncthreads();
        }

        const uint32_t stg = base + (uint32_t)s * STAGE_B;
        const uint32_t sA = stg, sB = stg + TILE_B;

#pragma unroll
        for (int kc = 0; kc < 2; kc++) {
            const uint32_t acol = (uint32_t)((2 * kc + wA) * 16);
            const uint32_t bcol = (uint32_t)((2 * kc + wB) * 16);
            uint32_t a[2][4];
#pragma unroll
            for (int mt = 0; mt < 2; mt++) {
                uint32_t ro = (uint32_t)((wm * 32 + mt * 16 + lrA) * ROWB);
                ldsm_x4(a[mt][0], a[mt][1], a[mt][2], a[mt][3], sA + ro + acol);
            }
            uint32_t b[4][4];
#pragma unroll
            for (int nt = 0; nt < 4; nt++) {
                uint32_t ro = (uint32_t)((wn * 64 + nt * 16 + lrB) * ROWB);
                ldsm_x4(b[nt][0], b[nt][1], b[nt][2], b[nt][3], sB + ro + bcol);
            }
#pragma unroll
            for (int mt = 0; mt < 2; mt++)
#pragma unroll
                for (int nt = 0; nt < 8; nt++) {
                    const int nn = nt >> 1, oc = (nt & 1) * 2;
                    mma_f16(c[mt][nt], a[mt], b[nn][oc], b[nn][oc + 1]);
                }
        }
        __syncthreads();
    }

    // epilogue
#pragma unroll
    for (int nt = 0; nt < 8; nt++) {
        const int col = n0 + wn * 64 + nt * 8 + tig * 2;
        if (col >= N) continue;
        float2 bb = make_float2(0.f, 0.f);
        if (hbias) bb = *(const float2*)(bias + col);
#pragma unroll
        for (int mt = 0; mt < 2; mt++) {
            const int r0 = m0 + wm * 32 + mt * 16 + gid;
            float v0 = c[mt][nt][0] + bb.x, v1 = c[mt][nt][1] + bb.y;
            float v2 = c[mt][nt][2] + bb.x, v3 = c[mt][nt][3] + bb.y;
            if (relu) {
                v0 = fmaxf(v0, 0.f); v1 = fmaxf(v1, 0.f);
                v2 = fmaxf(v2, 0.f); v3 = fmaxf(v3, 0.f);
            }
            if (r0 < M) {
                size_t o = (size_t)r0 * N + col;
                if (wf32) *(float2*)(C + o) = make_float2(v0, v1);
                if (wf16) *(uint32_t*)(Ch + o) = pack_h2(v0, v1);
            }
            if (r0 + 8 < M) {
                size_t o = (size_t)(r0 + 8) * N + col;
                if (wf32) *(float2*)(C + o) = make_float2(v2, v3);
                if (wf16) *(uint32_t*)(Ch + o) = pack_h2(v2, v3);
            }
        }
    }
}

// ---------------- conversion / elementwise kernels ----------------
__global__ void conv_h(const float4* __restrict__ src, uint32_t* __restrict__ dst, size_t n4)
{
    size_t t = (size_t)blockIdx.x * blockDim.x + threadIdx.x;
    if (t >= n4) return;
    float4 v = src[t];
    dst[t * 2]     = pack_h2(v.x, v.y);
    dst[t * 2 + 1] = pack_h2(v.z, v.w);
}

__global__ void conv_w(const float* __restrict__ src, int lds,
                       half_t* __restrict__ dst, int N, int K)
{
    int t = blockIdx.x * blockDim.x + threadIdx.x;
    if (t >= N * K) return;
    int r = t / K, cc = t % K;
    dst[t] = __float2half_rn(src[(size_t)r * lds + cc]);
}

__global__ void combine_wpi_h(const float* __restrict__ Wpi, half_t* __restrict__ dst)
{
    int t = blockIdx.x * blockDim.x + threadIdx.x;
    if (t >= EMB * EMB) return;
    int r = t / EMB, cc = t % EMB;
    dst[t] = __float2half_rn(Wpi[r * 600 + cc] + Wpi[r * 600 + 400 + cc]);
}

__global__ void gather_rows_f4(const float* __restrict__ src, const int* __restrict__ idx,
                               float* __restrict__ dst, int nrows)
{
    const int C4 = EMB / 4;
    int t = blockIdx.x * blockDim.x + threadIdx.x;
    if (t >= nrows * C4) return;
    int r = t / C4, cc = t % C4;
    ((float4*)dst)[t] = ((const float4*)src)[(size_t)idx[r] * C4 + cc];
}

__global__ void fuse_pi_h(const float* __restrict__ tmpP, const float* __restrict__ Acomb,
                          const int* __restrict__ rel_inds, const float* __restrict__ bias,
                          uint32_t* __restrict__ outh)
{
    const int C4 = EMB / 4;
    int t = blockIdx.x * blockDim.x + threadIdx.x;
    if (t >= N_REL * C4) return;
    int r = t / C4, cc = t % C4;
    int s = rel_inds[r * 3 + 1];
    float4 p = ((const float4*)tmpP)[t];
    float4 a = ((const float4*)Acomb)[(size_t)s * C4 + cc];
    float4 b = ((const float4*)bias)[cc];
    float v0 = fmaxf(p.x + a.x + b.x, 0.f), v1 = fmaxf(p.y + a.y + b.y, 0.f);
    float v2 = fmaxf(p.z + a.z + b.z, 0.f), v3 = fmaxf(p.w + a.w + b.w, 0.f);
    outh[t * 2]     = pack_h2(v0, v1);
    outh[t * 2 + 1] = pack_h2(v2, v3);
}

__global__ void fuse_po_h(const float* __restrict__ tmpQ, const float* __restrict__ Bsub,
                          const float* __restrict__ Bobj, const int* __restrict__ rel_inds,
                          const float* __restrict__ bias, uint32_t* __restrict__ outh)
{
    const int C4 = EMB / 4;
    int t = blockIdx.x * blockDim.x + threadIdx.x;
    if (t >= N_REL * C4) return;
    int r = t / C4, cc = t % C4;
    int s = rel_inds[r * 3 + 1];
    int o = rel_inds[r * 3 + 2];
    float4 q  = ((const float4*)tmpQ)[t];
    float4 bs = ((const float4*)Bsub)[(size_t)s * C4 + cc];
    float4 bo = ((const float4*)Bobj)[(size_t)o * C4 + cc];
    float4 b  = ((const float4*)bias)[cc];
    float v0 = fmaxf(q.x + bs.x + bo.x + b.x, 0.f), v1 = fmaxf(q.y + bs.y + bo.y + b.y, 0.f);
    float v2 = fmaxf(q.z + bs.z + bo.z + b.z, 0.f), v3 = fmaxf(q.w + bs.w + bo.w + b.w, 0.f);
    outh[t * 2]     = pack_h2(v0, v1);
    outh[t * 2 + 1] = pack_h2(v2, v3);
}

// ---------------- host side ----------------
template <typename T>
static T* sym(const void* s)
{
    void* p = nullptr;
    cudaGetSymbolAddress(&p, s);
    return (T*)p;
}

static void set_attrs()
{
    static bool done = false;
    if (!done) {
        cudaFuncSetAttribute(hmma_h<0>, cudaFuncAttributeMaxDynamicSharedMemorySize, SMEM_TOT);
        cudaFuncSetAttribute(hmma_h<1>, cudaFuncAttributeMaxDynamicSharedMemorySize, SMEM_TOT);
        done = true;
    }
}

static void gemmh(const half_t* A, const half_t* W, const float* bias,
                  float* C, half_t* Ch, int M, int N, int K, bool relu)
{
    set_attrs();
    dim3 grid((N + 127) / 128, (M + 127) / 128), block(256);
    hmma_h<0><<<grid, block, SMEM_TOT>>>(A, W, bias, C, Ch, M, N, K,
                                         relu ? 1 : 0, C ? 1 : 0, Ch ? 1 : 0, bias ? 1 : 0);
}

static void gemmh32(const float* A, const half_t* W, const float* bias,
                    float* C, half_t* Ch, int M, int N, int K, bool relu)
{
    set_attrs();
    dim3 grid((N + 127) / 128, (M + 127) / 128), block(256);
    hmma_h<1><<<grid, block, SMEM_TOT>>>(A, W, bias, C, Ch, M, N, K,
                                         relu ? 1 : 0, C ? 1 : 0, Ch ? 1 : 0, bias ? 1 : 0);
}

static void convw(const float* src, int lds, half_t* dst, int N, int K)
{
    int n = N * K;
    conv_w<<<(n + 255) / 256, 256>>>(src, lds, dst, N, K);
}

extern "C" void kernel_launch(void* const* d_in, const int* in_sizes, int n_in,
                              void* d_out, int out_size)
{
    (void)in_sizes; (void)n_in; (void)out_size;

    const float* obj_feats  = (const float*)d_in[1];
    const float* rel_feats  = (const float*)d_in[2];
    const int*   rel_inds   = (const int*)d_in[4];
    const int*   gt_rel     = (const int*)d_in[5];
    const int*   gt_obj     = (const int*)d_in[6];
    const float* obj_embed  = (const float*)d_in[7];
    const float* pred_embed = (const float*)d_in[8];
    const float* Wrs = (const float*)d_in[9];  const float* brs = (const float*)d_in[10];
    const float* Wos = (const float*)d_in[11]; const float* bos = (const float*)d_in[12];
    const float* Wso1= (const float*)d_in[13]; const float* bso1= (const float*)d_in[14];
    const float* Wso2= (const float*)d_in[15]; const float* bso2= (const float*)d_in[16];
    const float* Wsoo= (const float*)d_in[17]; const float* bsoo= (const float*)d_in[18];
    const float* Wp1 = (const float*)d_in[19]; const float* bp1 = (const float*)d_in[20];
    const float* Wp2 = (const float*)d_in[21]; const float* bp2 = (const float*)d_in[22];
    const float* Wpi = (const float*)d_in[23]; const float* bpi = (const float*)d_in[24];
    const float* Wpo1= (const float*)d_in[25]; const float* bpo1= (const float*)d_in[26];
    const float* Wpo2= (const float*)d_in[27]; const float* bpo2= (const float*)d_in[28];

    float* out = (float*)d_out;
    float* o_so_out   = out;                      // [50000,200]
    float* o_pred_out = out + 10000000;           // [200000,200]
    float* o_rel_sem  = out + 50000000;           // [200000,200]
    float* o_obj_sem  = out + 90000000;           // [50000,200]
    float* o_rel_gt   = out + 100000000;          // [51,200]
    float* o_obj_gt   = out + 100010200;          // [151,200]

    half_t *h1r = sym<half_t>(g_h1r_h), *h1o = sym<half_t>(g_h1o_h);
    half_t *pri = sym<half_t>(g_pri_h), *soi = sym<half_t>(g_soi_h);
    half_t *paf = sym<half_t>(g_paf_h), *soo = sym<half_t>(g_soo_h);
    half_t *hpo = sym<half_t>(g_hpo_h);
    half_t *pe = sym<half_t>(g_pe_h), *oe = sym<half_t>(g_oe_h);
    half_t *wrs = sym<half_t>(g_wrs), *wos = sym<half_t>(g_wos);
    half_t *wso1 = sym<half_t>(g_wso1), *wso2 = sym<half_t>(g_wso2);
    half_t *wsoo = sym<half_t>(g_wsoo);
    half_t *wp1 = sym<half_t>(g_wp1), *wp2 = sym<half_t>(g_wp2);
    half_t *wpip = sym<half_t>(g_wpip), *wcmb = sym<half_t>(g_wcmb);
    half_t *w1s = sym<half_t>(g_w1s), *w1p = sym<half_t>(g_w1p), *w1o = sym<half_t>(g_w1o);
    half_t *wpo2 = sym<half_t>(g_wpo2);
    float *Acomb = sym<float>(g_Acomb), *tmpP = sym<float>(g_tmpP);
    float *Bs = sym<float>(g_Bs), *Bo = sym<float>(g_Bo), *tmpQ = sym<float>(g_tmpQ);

    // ---- small conversions (embeds + weights) ----
    {
        size_t n4 = (size_t)N_PRED * EMB / 4;
        conv_h<<<(int)((n4 + 255) / 256), 256>>>((const float4*)pred_embed, (uint32_t*)pe, n4);
        n4 = (size_t)N_CLS * EMB / 4;
        conv_h<<<(int)((n4 + 255) / 256), 256>>>((const float4*)obj_embed, (uint32_t*)oe, n4);
    }
    convw(Wrs, EMB, wrs, EMB, EMB);
    convw(Wos, EMB, wos, EMB, EMB);
    convw(Wso1, FEAT, wso1, INTER, FEAT);
    convw(Wso2, INTER, wso2, EMB, INTER);
    convw(Wsoo, EMB, wsoo, EMB, EMB);
    convw(Wp1, FEAT, wp1, INTER, FEAT);
    convw(Wp2, INTER, wp2, EMB, INTER);
    convw(Wpi + EMB, 600, wpip, EMB, EMB);
    convw(Wpo1, 600, w1s, EMB, EMB);
    convw(Wpo1 + EMB, 600, w1p, EMB, EMB);
    convw(Wpo1 + 2 * EMB, 600, w1o, EMB, EMB);
    convw(Wpo2, EMB, wpo2, EMB, EMB);
    combine_wpi_h<<<(EMB * EMB + 255) / 256, 256>>>(Wpi, wcmb);

    // ---- semantic tables + gathers ----
    gemmh(pe, wrs, brs, o_rel_gt, nullptr, N_PRED, EMB, EMB, false);
    gemmh(oe, wos, bos, o_obj_gt, nullptr, N_CLS, EMB, EMB, false);
    gather_rows_f4<<<(N_REL * (EMB / 4) + 255) / 256, 256>>>(o_rel_gt, gt_rel, o_rel_sem, N_REL);
    gather_rows_f4<<<(N_OBJ * (EMB / 4) + 255) / 256, 256>>>(o_obj_gt, gt_obj, o_obj_sem, N_OBJ);

    // ---- object path (layer 1 reads fp32 directly) ----
    gemmh32(obj_feats, wso1, bso1, nullptr, h1o, N_OBJ, INTER, FEAT, true);
    gemmh(h1o, wso2, bso2, nullptr, soi, N_OBJ, EMB, INTER, true);
    gemmh(soi, wsoo, bsoo, o_so_out, soo, N_OBJ, EMB, EMB, false);

    // ---- relation path (layer 1 reads fp32 directly) ----
    gemmh32(rel_feats, wp1, bp1, nullptr, h1r, N_REL, INTER, FEAT, true);
    gemmh(h1r, wp2, bp2, nullptr, pri, N_REL, EMB, INTER, true);

    // ---- pred_inter_af (factored concat; obj slice == sub slice index) ----
    gemmh(soi, wcmb, nullptr, Acomb, nullptr, N_OBJ, EMB, EMB, false);
    gemmh(pri, wpip, nullptr, tmpP, nullptr, N_REL, EMB, EMB, false);
    fuse_pi_h<<<(N_REL * (EMB / 4) + 255) / 256, 256>>>(tmpP, Acomb, rel_inds, bpi,
                                                        (uint32_t*)paf);

    // ---- pred_out (factored concat) ----
    gemmh(soo, w1s, nullptr, Bs, nullptr, N_OBJ, EMB, EMB, false);
    gemmh(soo, w1o, nullptr, Bo, nullptr, N_OBJ, EMB, EMB, false);
    gemmh(paf, w1p, nullptr, tmpQ, nullptr, N_REL, EMB, EMB, false);
    fuse_po_h<<<(N_REL * (EMB / 4) + 255) / 256, 256>>>(tmpQ, Bs, Bo, rel_inds, bpo1,
                                                        (uint32_t*)hpo);
    gemmh(hpo, wpo2, bpo2, o_pred_out, nullptr, N_REL, EMB, EMB, false);
}